// round 1
// baseline (speedup 1.0000x reference)
#include <cuda_runtime.h>
#include <math.h>

#define MAXN   120000
#define SLOPEF 0.01f
#define EPSF   1e-6f

// ---------------- device scratch (static, no allocs) ----------------
__device__ float g_viA[MAXN * 192];   // att1 vi, later reused as net2 vi
__device__ float g_viN[MAXN * 192];   // net1 vi
__device__ float g_Xa [MAXN * 320];   // [vnorm | sca] att branch, later X2 (net2 input)
__device__ float g_Xn [MAXN * 320];   // [vnorm | sca] net branch
__device__ float g_Sa [MAXN * 256];   // att1 out_sca, later fs
__device__ float g_Sn [MAXN * 256];   // net1 out_sca
__device__ float g_Ga [MAXN * 64];    // gates (att1, later net2)
__device__ float g_Gn [MAXN * 64];    // gates (net1)
__device__ float g_va [MAXN * 192];   // v after vn_lrelu (att), later fv
__device__ float g_vn [MAXN * 192];   // v after vn_lrelu (net)
__device__ float g_att[MAXN];
__device__ float g_w  [MAXN];
__device__ int   g_segstart[4100];

// ---------------- helpers ----------------
__device__ __forceinline__ void load_wt_transposed(const float* __restrict__ W,
                                                   float* __restrict__ Wt,
                                                   int tid, int nthreads) {
    // W is (64,64) row-major [o][c]; store Wt[c*64+o]
    for (int i = tid; i < 4096; i += nthreads) {
        int o = i >> 6, c = i & 63;
        Wt[c * 64 + o] = W[i];
    }
}

// ============================================================================
// K1: front — sca = h_sca + te[t]; viA = a1Wv1@vec; viN = n1Wv1@vec;
//     Xa = [|viA|, sca]; Xn = [|viN|, sca]
// warp-per-node, 8 nodes per 256-thread block
// ============================================================================
__global__ void k_front(const float* __restrict__ h_sca, const float* __restrict__ h_vec,
                        const float* __restrict__ te, const int* __restrict__ tptr,
                        const float* __restrict__ Wv1a, const float* __restrict__ Wv1n,
                        float* __restrict__ viA, float* __restrict__ viN,
                        float* __restrict__ Xa, float* __restrict__ Xn, int n) {
    __shared__ float WtA[4096];
    __shared__ float WtN[4096];
    __shared__ float vecS[8][192];
    int tid = threadIdx.x, w = tid >> 5, lane = tid & 31;
    load_wt_transposed(Wv1a, WtA, tid, 256);
    load_wt_transposed(Wv1n, WtN, tid, 256);
    __syncthreads();

    int node = blockIdx.x * 8 + w;
    if (node >= n) return;
    int t = *tptr;

    const float* vv = h_vec + (size_t)node * 192;
    for (int i = lane; i < 192; i += 32) vecS[w][i] = vv[i];

    const float* hs  = h_sca + (size_t)node * 256;
    const float* teb = te + (size_t)t * 256;
    float* xa = Xa + (size_t)node * 320;
    float* xn = Xn + (size_t)node * 320;
    for (int k = lane; k < 256; k += 32) {
        float s = hs[k] + teb[k];
        xa[64 + k] = s;
        xn[64 + k] = s;
    }
    __syncwarp();

    float aA0[3] = {0,0,0}, aA1[3] = {0,0,0};
    float aN0[3] = {0,0,0}, aN1[3] = {0,0,0};
#pragma unroll 8
    for (int c = 0; c < 64; c++) {
        float v0 = vecS[w][c*3+0], v1 = vecS[w][c*3+1], v2 = vecS[w][c*3+2];
        float wa0 = WtA[c*64 + lane],      wa1 = WtA[c*64 + lane + 32];
        float wn0 = WtN[c*64 + lane],      wn1 = WtN[c*64 + lane + 32];
        aA0[0] = fmaf(wa0, v0, aA0[0]); aA0[1] = fmaf(wa0, v1, aA0[1]); aA0[2] = fmaf(wa0, v2, aA0[2]);
        aA1[0] = fmaf(wa1, v0, aA1[0]); aA1[1] = fmaf(wa1, v1, aA1[1]); aA1[2] = fmaf(wa1, v2, aA1[2]);
        aN0[0] = fmaf(wn0, v0, aN0[0]); aN0[1] = fmaf(wn0, v1, aN0[1]); aN0[2] = fmaf(wn0, v2, aN0[2]);
        aN1[0] = fmaf(wn1, v0, aN1[0]); aN1[1] = fmaf(wn1, v1, aN1[1]); aN1[2] = fmaf(wn1, v2, aN1[2]);
    }
    float* vaP = viA + (size_t)node * 192;
    float* vnP = viN + (size_t)node * 192;
#pragma unroll
    for (int d = 0; d < 3; d++) {
        vaP[lane*3 + d]      = aA0[d];
        vaP[(lane+32)*3 + d] = aA1[d];
        vnP[lane*3 + d]      = aN0[d];
        vnP[(lane+32)*3 + d] = aN1[d];
    }
    xa[lane]      = sqrtf(aA0[0]*aA0[0] + aA0[1]*aA0[1] + aA0[2]*aA0[2]);
    xa[lane + 32] = sqrtf(aA1[0]*aA1[0] + aA1[1]*aA1[1] + aA1[2]*aA1[2]);
    xn[lane]      = sqrtf(aN0[0]*aN0[0] + aN0[1]*aN0[1] + aN0[2]*aN0[2]);
    xn[lane + 32] = sqrtf(aN1[0]*aN1[0] + aN1[1]*aN1[1] + aN1[2]*aN1[2]);
}

// ============================================================================
// GEMM: C[M,Nc] = act(A[M,K] @ W[Nc,K]^T (+bias))    (both row-major, NT)
// 64x64x16 tile, 256 threads, 4x4 per thread.  ACT: 0=none, 1=sigmoid(+bias)
// ============================================================================
template <int ACT>
__global__ void gemm_nt(const float* __restrict__ A, const float* __restrict__ W,
                        const float* __restrict__ bias, float* __restrict__ C,
                        int M, int Nc, int K) {
    __shared__ float As[16][64];
    __shared__ float Bs[16][64];
    int m0 = blockIdx.x * 64, n0 = blockIdx.y * 64;
    int tid = threadIdx.x;
    int tm = (tid >> 4) << 2;
    int tn = (tid & 15) << 2;
    float acc[4][4];
#pragma unroll
    for (int x = 0; x < 4; x++)
#pragma unroll
        for (int y = 0; y < 4; y++) acc[x][y] = 0.f;

    int li = tid >> 2;          // 0..63 row in tile
    int lj = (tid & 3) << 2;    // 0,4,8,12

    for (int k0 = 0; k0 < K; k0 += 16) {
        int m = m0 + li;
        float4 v = (m < M) ? *(const float4*)(A + (size_t)m * K + k0 + lj)
                           : make_float4(0.f, 0.f, 0.f, 0.f);
        As[lj + 0][li] = v.x; As[lj + 1][li] = v.y; As[lj + 2][li] = v.z; As[lj + 3][li] = v.w;
        float4 u = *(const float4*)(W + (size_t)(n0 + li) * K + k0 + lj);
        Bs[lj + 0][li] = u.x; Bs[lj + 1][li] = u.y; Bs[lj + 2][li] = u.z; Bs[lj + 3][li] = u.w;
        __syncthreads();
#pragma unroll
        for (int kk = 0; kk < 16; kk++) {
            float a[4], b[4];
            *(float4*)a = *(const float4*)&As[kk][tm];
            *(float4*)b = *(const float4*)&Bs[kk][tn];
#pragma unroll
            for (int x = 0; x < 4; x++)
#pragma unroll
                for (int y = 0; y < 4; y++)
                    acc[x][y] = fmaf(a[x], b[y], acc[x][y]);
        }
        __syncthreads();
    }
#pragma unroll
    for (int x = 0; x < 4; x++) {
        int m = m0 + tm + x;
        if (m >= M) continue;
#pragma unroll
        for (int y = 0; y < 4; y++) {
            int nn = n0 + tn + y;
            float r = acc[x][y];
            if (ACT == 1) {
                r += bias[nn];
                r = 1.f / (1.f + __expf(-r));
            }
            C[(size_t)m * Nc + nn] = r;
        }
    }
}

// ============================================================================
// K3: u = G * (Wv2 @ vi); if useWd: out = vn_lrelu(Wd, u) else out = u
// warp-per-node
// ============================================================================
__global__ void k_gatevn(const float* __restrict__ vi, const float* __restrict__ G,
                         const float* __restrict__ Wv2, const float* __restrict__ Wd,
                         float* __restrict__ out, int n, int useWd) {
    __shared__ float Wt2[4096];
    __shared__ float WtD[4096];
    __shared__ float viS[8][192];
    __shared__ float uS[8][192];
    int tid = threadIdx.x, w = tid >> 5, lane = tid & 31;
    load_wt_transposed(Wv2, Wt2, tid, 256);
    if (useWd) load_wt_transposed(Wd, WtD, tid, 256);
    __syncthreads();

    int node = blockIdx.x * 8 + w;
    if (node >= n) return;

    const float* vv = vi + (size_t)node * 192;
    for (int i = lane; i < 192; i += 32) viS[w][i] = vv[i];
    __syncwarp();

    float u0[3] = {0,0,0}, u1[3] = {0,0,0};
#pragma unroll 8
    for (int c = 0; c < 64; c++) {
        float v0 = viS[w][c*3+0], v1 = viS[w][c*3+1], v2 = viS[w][c*3+2];
        float w0 = Wt2[c*64 + lane], w1 = Wt2[c*64 + lane + 32];
        u0[0] = fmaf(w0, v0, u0[0]); u0[1] = fmaf(w0, v1, u0[1]); u0[2] = fmaf(w0, v2, u0[2]);
        u1[0] = fmaf(w1, v0, u1[0]); u1[1] = fmaf(w1, v1, u1[1]); u1[2] = fmaf(w1, v2, u1[2]);
    }
    float g0 = G[(size_t)node * 64 + lane];
    float g1 = G[(size_t)node * 64 + lane + 32];
#pragma unroll
    for (int d = 0; d < 3; d++) { u0[d] *= g0; u1[d] *= g1; }

    float* op = out + (size_t)node * 192;
    if (!useWd) {
#pragma unroll
        for (int d = 0; d < 3; d++) {
            op[lane*3 + d]      = u0[d];
            op[(lane+32)*3 + d] = u1[d];
        }
        return;
    }
#pragma unroll
    for (int d = 0; d < 3; d++) {
        uS[w][lane*3 + d]      = u0[d];
        uS[w][(lane+32)*3 + d] = u1[d];
    }
    __syncwarp();

    float d0[3] = {0,0,0}, d1[3] = {0,0,0};
#pragma unroll 8
    for (int c = 0; c < 64; c++) {
        float v0 = uS[w][c*3+0], v1 = uS[w][c*3+1], v2 = uS[w][c*3+2];
        float w0 = WtD[c*64 + lane], w1 = WtD[c*64 + lane + 32];
        d0[0] = fmaf(w0, v0, d0[0]); d0[1] = fmaf(w0, v1, d0[1]); d0[2] = fmaf(w0, v2, d0[2]);
        d1[0] = fmaf(w1, v0, d1[0]); d1[1] = fmaf(w1, v1, d1[1]); d1[2] = fmaf(w1, v2, d1[2]);
    }
    // vn_lrelu on (u, d) per channel
    {
        float dot = u0[0]*d0[0] + u0[1]*d0[1] + u0[2]*d0[2];
        float dsq = d0[0]*d0[0] + d0[1]*d0[1] + d0[2]*d0[2];
        float s   = dot / (dsq + EPSF);
#pragma unroll
        for (int d = 0; d < 3; d++) {
            float x = u0[d];
            float proj = x - s * d0[d];
            float r = (dot >= 0.f) ? x : (SLOPEF * x + (1.f - SLOPEF) * proj);
            op[lane*3 + d] = r;
        }
    }
    {
        float dot = u1[0]*d1[0] + u1[1]*d1[1] + u1[2]*d1[2];
        float dsq = d1[0]*d1[0] + d1[1]*d1[1] + d1[2]*d1[2];
        float s   = dot / (dsq + EPSF);
#pragma unroll
        for (int d = 0; d < 3; d++) {
            float x = u1[d];
            float proj = x - s * d1[d];
            float r = (dot >= 0.f) ? x : (SLOPEF * x + (1.f - SLOPEF) * proj);
            op[(lane+32)*3 + d] = r;
        }
    }
}

// ============================================================================
// K4: att[n] = Ws0[0:64] . |a2Wv1 @ v|  +  Ws0[64:320] . lrelu(Sa[n])
// warp-per-node
// ============================================================================
__global__ void k_att(const float* __restrict__ v, const float* __restrict__ Wv1,
                      const float* __restrict__ Ws, const float* __restrict__ S,
                      float* __restrict__ att, int n) {
    __shared__ float Wt[4096];
    __shared__ float wsS[320];
    __shared__ float vS[8][192];
    int tid = threadIdx.x, w = tid >> 5, lane = tid & 31;
    load_wt_transposed(Wv1, Wt, tid, 256);
    for (int i = tid; i < 320; i += 256) wsS[i] = Ws[i];
    __syncthreads();

    int node = blockIdx.x * 8 + w;
    if (node >= n) return;

    const float* vv = v + (size_t)node * 192;
    for (int i = lane; i < 192; i += 32) vS[w][i] = vv[i];
    __syncwarp();

    float a0[3] = {0,0,0}, a1[3] = {0,0,0};
#pragma unroll 8
    for (int c = 0; c < 64; c++) {
        float v0 = vS[w][c*3+0], v1 = vS[w][c*3+1], v2 = vS[w][c*3+2];
        float w0 = Wt[c*64 + lane], w1 = Wt[c*64 + lane + 32];
        a0[0] = fmaf(w0, v0, a0[0]); a0[1] = fmaf(w0, v1, a0[1]); a0[2] = fmaf(w0, v2, a0[2]);
        a1[0] = fmaf(w1, v0, a1[0]); a1[1] = fmaf(w1, v1, a1[1]); a1[2] = fmaf(w1, v2, a1[2]);
    }
    float n0 = sqrtf(a0[0]*a0[0] + a0[1]*a0[1] + a0[2]*a0[2]);
    float n1 = sqrtf(a1[0]*a1[0] + a1[1]*a1[1] + a1[2]*a1[2]);
    float p = wsS[lane] * n0 + wsS[lane + 32] * n1;
    const float* s = S + (size_t)node * 256;
    for (int k = lane; k < 256; k += 32) {
        float sv = s[k];
        sv = (sv >= 0.f) ? sv : SLOPEF * sv;
        p = fmaf(wsS[64 + k], sv, p);
    }
#pragma unroll
    for (int o = 16; o > 0; o >>= 1) p += __shfl_down_sync(0xffffffff, p, o);
    if (lane == 0) att[node] = p;
}

// ============================================================================
// K5: vi2 = n2Wv1 @ v ; X2 = [|vi2|, lrelu(Sn)]
// ============================================================================
__global__ void k_vn3n(const float* __restrict__ v, const float* __restrict__ Wv1,
                       const float* __restrict__ S,
                       float* __restrict__ vi2, float* __restrict__ X2, int n) {
    __shared__ float Wt[4096];
    __shared__ float vS[8][192];
    int tid = threadIdx.x, w = tid >> 5, lane = tid & 31;
    load_wt_transposed(Wv1, Wt, tid, 256);
    __syncthreads();

    int node = blockIdx.x * 8 + w;
    if (node >= n) return;

    const float* vv = v + (size_t)node * 192;
    for (int i = lane; i < 192; i += 32) vS[w][i] = vv[i];

    float* x2 = X2 + (size_t)node * 320;
    const float* s = S + (size_t)node * 256;
    for (int k = lane; k < 256; k += 32) {
        float sv = s[k];
        x2[64 + k] = (sv >= 0.f) ? sv : SLOPEF * sv;
    }
    __syncwarp();

    float a0[3] = {0,0,0}, a1[3] = {0,0,0};
#pragma unroll 8
    for (int c = 0; c < 64; c++) {
        float v0 = vS[w][c*3+0], v1 = vS[w][c*3+1], v2 = vS[w][c*3+2];
        float w0 = Wt[c*64 + lane], w1 = Wt[c*64 + lane + 32];
        a0[0] = fmaf(w0, v0, a0[0]); a0[1] = fmaf(w0, v1, a0[1]); a0[2] = fmaf(w0, v2, a0[2]);
        a1[0] = fmaf(w1, v0, a1[0]); a1[1] = fmaf(w1, v1, a1[1]); a1[2] = fmaf(w1, v2, a1[2]);
    }
    float* vp = vi2 + (size_t)node * 192;
#pragma unroll
    for (int d = 0; d < 3; d++) {
        vp[lane*3 + d]      = a0[d];
        vp[(lane+32)*3 + d] = a1[d];
    }
    x2[lane]      = sqrtf(a0[0]*a0[0] + a0[1]*a0[1] + a0[2]*a0[2]);
    x2[lane + 32] = sqrtf(a1[0]*a1[0] + a1[1]*a1[1] + a1[2]*a1[2]);
}

// ============================================================================
// segment offsets (batch_id sorted): start[b] = lower_bound(bid, b), start[B]=n
// ============================================================================
__global__ void k_segstart(const int* __restrict__ bid, int n, int B, int* __restrict__ start) {
    int b = blockIdx.x * blockDim.x + threadIdx.x;
    if (b > B) return;
    int lo = 0, hi = n;
    while (lo < hi) {
        int mid = (lo + hi) >> 1;
        if (bid[mid] < b) lo = mid + 1; else hi = mid;
    }
    start[b] = lo;
}

// ============================================================================
// segment softmax: one block per segment
// ============================================================================
__global__ void k_softmax(const float* __restrict__ att, const int* __restrict__ start,
                          float* __restrict__ w) {
    int b = blockIdx.x;
    int s = start[b], e = start[b + 1];
    if (s >= e) return;
    __shared__ float red[256];
    int tid = threadIdx.x;
    float m = -INFINITY;
    for (int i = s + tid; i < e; i += 256) m = fmaxf(m, att[i]);
    red[tid] = m; __syncthreads();
    for (int o = 128; o > 0; o >>= 1) {
        if (tid < o) red[tid] = fmaxf(red[tid], red[tid + o]);
        __syncthreads();
    }
    m = red[0]; __syncthreads();
    float zs = 0.f;
    for (int i = s + tid; i < e; i += 256) zs += __expf(att[i] - m);
    red[tid] = zs; __syncthreads();
    for (int o = 128; o > 0; o >>= 1) {
        if (tid < o) red[tid] += red[tid + o];
        __syncthreads();
    }
    float z = red[0];
    float inv = 1.f / z;
    for (int i = s + tid; i < e; i += 256) w[i] = __expf(att[i] - m) * inv;
}

// ============================================================================
// weighted segment reduce: one block (256 thr) per segment
// out layout: [B,256] feat | [B,64,3] vec | [B,3] pos
// ============================================================================
__global__ void k_reduce(const float* __restrict__ w, const float* __restrict__ fs,
                         const float* __restrict__ fv, const float* __restrict__ pos,
                         const int* __restrict__ start, int B, float* __restrict__ out) {
    int b = blockIdx.x, j = threadIdx.x;
    int s = start[b], e = start[b + 1];
    float a256 = 0.f, a192 = 0.f, a3 = 0.f;
    for (int i = s; i < e; i++) {
        float wi = w[i];
        a256 = fmaf(wi, fs[(size_t)i * 256 + j], a256);
        if (j < 192) a192 = fmaf(wi, fv[(size_t)i * 192 + j], a192);
        if (j < 3)   a3   = fmaf(wi, pos[(size_t)i * 3 + j], a3);
    }
    out[(size_t)b * 256 + j] = a256;
    if (j < 192) out[(size_t)B * 256 + (size_t)b * 192 + j] = a192;
    if (j < 3)   out[(size_t)B * 256 + (size_t)B * 192 + (size_t)b * 3 + j] = a3;
}

// ============================================================================
// launch
// ============================================================================
extern "C" void kernel_launch(void* const* d_in, const int* in_sizes, int n_in,
                              void* d_out, int out_size) {
    const float* h_sca = (const float*)d_in[0];
    const float* h_vec = (const float*)d_in[1];
    const float* pos   = (const float*)d_in[2];
    const float* te    = (const float*)d_in[3];
    const float* a1Wv1 = (const float*)d_in[4];
    const float* a1Wv2 = (const float*)d_in[5];
    const float* a1Ws  = (const float*)d_in[6];
    const float* a1Wg  = (const float*)d_in[7];
    const float* a1bg  = (const float*)d_in[8];
    const float* a1Wd  = (const float*)d_in[9];
    const float* a2Wv1 = (const float*)d_in[10];
    const float* a2Ws  = (const float*)d_in[12];
    const float* n1Wv1 = (const float*)d_in[15];
    const float* n1Wv2 = (const float*)d_in[16];
    const float* n1Ws  = (const float*)d_in[17];
    const float* n1Wg  = (const float*)d_in[18];
    const float* n1bg  = (const float*)d_in[19];
    const float* n1Wd  = (const float*)d_in[20];
    const float* n2Wv1 = (const float*)d_in[21];
    const float* n2Wv2 = (const float*)d_in[22];
    const float* n2Ws  = (const float*)d_in[23];
    const float* n2Wg  = (const float*)d_in[24];
    const float* n2bg  = (const float*)d_in[25];
    const int*   tptr  = (const int*)d_in[26];
    const int*   bid   = (const int*)d_in[27];

    int n = in_sizes[0] / 256;
    int B = out_size / 451;   // 256 + 192 + 3

    float *viA, *viN, *Xa, *Xn, *Sa, *Sn, *Ga, *Gn, *va, *vnn, *att, *w;
    int* segs;
    cudaGetSymbolAddress((void**)&viA, g_viA);
    cudaGetSymbolAddress((void**)&viN, g_viN);
    cudaGetSymbolAddress((void**)&Xa,  g_Xa);
    cudaGetSymbolAddress((void**)&Xn,  g_Xn);
    cudaGetSymbolAddress((void**)&Sa,  g_Sa);
    cudaGetSymbolAddress((void**)&Sn,  g_Sn);
    cudaGetSymbolAddress((void**)&Ga,  g_Ga);
    cudaGetSymbolAddress((void**)&Gn,  g_Gn);
    cudaGetSymbolAddress((void**)&va,  g_va);
    cudaGetSymbolAddress((void**)&vnn, g_vn);
    cudaGetSymbolAddress((void**)&att, g_att);
    cudaGetSymbolAddress((void**)&w,   g_w);
    cudaGetSymbolAddress((void**)&segs, g_segstart);

    int nb8 = (n + 7) / 8;
    dim3 gS((n + 63) / 64, 4);   // Nc=256
    dim3 gG((n + 63) / 64, 1);   // Nc=64

    // front: vi + X for both branches
    k_front<<<nb8, 256>>>(h_sca, h_vec, te, tptr, a1Wv1, n1Wv1, viA, viN, Xa, Xn, n);
    // out_sca GEMMs
    gemm_nt<0><<<gS, 256>>>(Xa, a1Ws, nullptr, Sa, n, 256, 320);
    gemm_nt<0><<<gS, 256>>>(Xn, n1Ws, nullptr, Sn, n, 256, 320);
    // gates
    gemm_nt<1><<<gG, 256>>>(Sa, a1Wg, a1bg, Ga, n, 64, 256);
    gemm_nt<1><<<gG, 256>>>(Sn, n1Wg, n1bg, Gn, n, 64, 256);
    // gated Wv2 + vn_lrelu
    k_gatevn<<<nb8, 256>>>(viA, Ga, a1Wv2, a1Wd, va,  n, 1);
    k_gatevn<<<nb8, 256>>>(viN, Gn, n1Wv2, n1Wd, vnn, n, 1);
    // attention scalar
    k_att<<<nb8, 256>>>(va, a2Wv1, a2Ws, Sa, att, n);
    // net2 front (reuse viA as vi2, Xa as X2)
    k_vn3n<<<nb8, 256>>>(vnn, n2Wv1, Sn, viA, Xa, n);
    // fs (reuse Sa), gate2 (reuse Ga), fv (reuse va)
    gemm_nt<0><<<gS, 256>>>(Xa, n2Ws, nullptr, Sa, n, 256, 320);
    gemm_nt<1><<<gG, 256>>>(Sa, n2Wg, n2bg, Ga, n, 64, 256);
    k_gatevn<<<nb8, 256>>>(viA, Ga, n2Wv2, nullptr, va, n, 0);
    // segment softmax + weighted reduce
    k_segstart<<<(B + 1 + 255) / 256, 256>>>(bid, n, B, segs);
    k_softmax<<<B, 256>>>(att, segs, w);
    k_reduce<<<B, 256>>>(w, Sa, va, pos, segs, B, (float*)d_out);
}

// round 2
// speedup vs baseline: 1.0001x; 1.0001x over previous
#include <cuda_runtime.h>
#include <math.h>

#define MAXN   120000
#define SLOPEF 0.01f
#define EPSF   1e-6f

// ---------------- device scratch (static, no allocs) ----------------
__device__ float g_viA[MAXN * 192];   // att1 vi, later reused as net2 vi
__device__ float g_viN[MAXN * 192];   // net1 vi
__device__ float g_Xa [MAXN * 320];   // [vnorm | sca] att branch, later X2 (net2 input)
__device__ float g_Xn [MAXN * 320];   // [vnorm | sca] net branch
__device__ float g_Sa [MAXN * 256];   // att1 out_sca, later fs
__device__ float g_Sn [MAXN * 256];   // net1 out_sca
__device__ float g_Ga [MAXN * 64];    // gates (att1, later net2)
__device__ float g_Gn [MAXN * 64];    // gates (net1)
__device__ float g_va [MAXN * 192];   // v after vn_lrelu (att), later fv
__device__ float g_vn [MAXN * 192];   // v after vn_lrelu (net)
__device__ float g_att[MAXN];
__device__ float g_w  [MAXN];
__device__ int   g_segstart[4100];

// ---------------- helpers ----------------
__device__ __forceinline__ void load_wt_transposed(const float* __restrict__ W,
                                                   float* __restrict__ Wt,
                                                   int tid, int nthreads) {
    // W is (64,64) row-major [o][c]; store Wt[c*64+o]
    for (int i = tid; i < 4096; i += nthreads) {
        int o = i >> 6, c = i & 63;
        Wt[c * 64 + o] = W[i];
    }
}

// ============================================================================
// K1: front — sca = h_sca + te[t]; viA = a1Wv1@vec; viN = n1Wv1@vec;
//     Xa = [|viA|, sca]; Xn = [|viN|, sca]
// warp-per-node, 8 nodes per 256-thread block
// ============================================================================
__global__ void k_front(const float* __restrict__ h_sca, const float* __restrict__ h_vec,
                        const float* __restrict__ te, const int* __restrict__ tptr,
                        const float* __restrict__ Wv1a, const float* __restrict__ Wv1n,
                        float* __restrict__ viA, float* __restrict__ viN,
                        float* __restrict__ Xa, float* __restrict__ Xn, int n) {
    __shared__ float WtA[4096];
    __shared__ float WtN[4096];
    __shared__ float vecS[8][192];
    int tid = threadIdx.x, w = tid >> 5, lane = tid & 31;
    load_wt_transposed(Wv1a, WtA, tid, 256);
    load_wt_transposed(Wv1n, WtN, tid, 256);
    __syncthreads();

    int node = blockIdx.x * 8 + w;
    if (node >= n) return;
    int t = *tptr;

    const float* vv = h_vec + (size_t)node * 192;
    for (int i = lane; i < 192; i += 32) vecS[w][i] = vv[i];

    const float* hs  = h_sca + (size_t)node * 256;
    const float* teb = te + (size_t)t * 256;
    float* xa = Xa + (size_t)node * 320;
    float* xn = Xn + (size_t)node * 320;
    for (int k = lane; k < 256; k += 32) {
        float s = hs[k] + teb[k];
        xa[64 + k] = s;
        xn[64 + k] = s;
    }
    __syncwarp();

    float aA0[3] = {0,0,0}, aA1[3] = {0,0,0};
    float aN0[3] = {0,0,0}, aN1[3] = {0,0,0};
#pragma unroll 8
    for (int c = 0; c < 64; c++) {
        float v0 = vecS[w][c*3+0], v1 = vecS[w][c*3+1], v2 = vecS[w][c*3+2];
        float wa0 = WtA[c*64 + lane],      wa1 = WtA[c*64 + lane + 32];
        float wn0 = WtN[c*64 + lane],      wn1 = WtN[c*64 + lane + 32];
        aA0[0] = fmaf(wa0, v0, aA0[0]); aA0[1] = fmaf(wa0, v1, aA0[1]); aA0[2] = fmaf(wa0, v2, aA0[2]);
        aA1[0] = fmaf(wa1, v0, aA1[0]); aA1[1] = fmaf(wa1, v1, aA1[1]); aA1[2] = fmaf(wa1, v2, aA1[2]);
        aN0[0] = fmaf(wn0, v0, aN0[0]); aN0[1] = fmaf(wn0, v1, aN0[1]); aN0[2] = fmaf(wn0, v2, aN0[2]);
        aN1[0] = fmaf(wn1, v0, aN1[0]); aN1[1] = fmaf(wn1, v1, aN1[1]); aN1[2] = fmaf(wn1, v2, aN1[2]);
    }
    float* vaP = viA + (size_t)node * 192;
    float* vnP = viN + (size_t)node * 192;
#pragma unroll
    for (int d = 0; d < 3; d++) {
        vaP[lane*3 + d]      = aA0[d];
        vaP[(lane+32)*3 + d] = aA1[d];
        vnP[lane*3 + d]      = aN0[d];
        vnP[(lane+32)*3 + d] = aN1[d];
    }
    xa[lane]      = sqrtf(aA0[0]*aA0[0] + aA0[1]*aA0[1] + aA0[2]*aA0[2]);
    xa[lane + 32] = sqrtf(aA1[0]*aA1[0] + aA1[1]*aA1[1] + aA1[2]*aA1[2]);
    xn[lane]      = sqrtf(aN0[0]*aN0[0] + aN0[1]*aN0[1] + aN0[2]*aN0[2]);
    xn[lane + 32] = sqrtf(aN1[0]*aN1[0] + aN1[1]*aN1[1] + aN1[2]*aN1[2]);
}

// ============================================================================
// GEMM: C[M,Nc] = act(A[M,K] @ W[Nc,K]^T (+bias))    (both row-major, NT)
// 64x64x16 tile, 256 threads, 4x4 per thread.  ACT: 0=none, 1=sigmoid(+bias)
// ============================================================================
template <int ACT>
__global__ void gemm_nt(const float* __restrict__ A, const float* __restrict__ W,
                        const float* __restrict__ bias, float* __restrict__ C,
                        int M, int Nc, int K) {
    __shared__ float As[16][64];
    __shared__ float Bs[16][64];
    int m0 = blockIdx.x * 64, n0 = blockIdx.y * 64;
    int tid = threadIdx.x;
    int tm = (tid >> 4) << 2;
    int tn = (tid & 15) << 2;
    float acc[4][4];
#pragma unroll
    for (int x = 0; x < 4; x++)
#pragma unroll
        for (int y = 0; y < 4; y++) acc[x][y] = 0.f;

    int li = tid >> 2;          // 0..63 row in tile
    int lj = (tid & 3) << 2;    // 0,4,8,12

    for (int k0 = 0; k0 < K; k0 += 16) {
        int m = m0 + li;
        float4 v = (m < M) ? *(const float4*)(A + (size_t)m * K + k0 + lj)
                           : make_float4(0.f, 0.f, 0.f, 0.f);
        As[lj + 0][li] = v.x; As[lj + 1][li] = v.y; As[lj + 2][li] = v.z; As[lj + 3][li] = v.w;
        float4 u = *(const float4*)(W + (size_t)(n0 + li) * K + k0 + lj);
        Bs[lj + 0][li] = u.x; Bs[lj + 1][li] = u.y; Bs[lj + 2][li] = u.z; Bs[lj + 3][li] = u.w;
        __syncthreads();
#pragma unroll
        for (int kk = 0; kk < 16; kk++) {
            float a[4], b[4];
            *(float4*)a = *(const float4*)&As[kk][tm];
            *(float4*)b = *(const float4*)&Bs[kk][tn];
#pragma unroll
            for (int x = 0; x < 4; x++)
#pragma unroll
                for (int y = 0; y < 4; y++)
                    acc[x][y] = fmaf(a[x], b[y], acc[x][y]);
        }
        __syncthreads();
    }
#pragma unroll
    for (int x = 0; x < 4; x++) {
        int m = m0 + tm + x;
        if (m >= M) continue;
#pragma unroll
        for (int y = 0; y < 4; y++) {
            int nn = n0 + tn + y;
            float r = acc[x][y];
            if (ACT == 1) {
                r += bias[nn];
                r = 1.f / (1.f + __expf(-r));
            }
            C[(size_t)m * Nc + nn] = r;
        }
    }
}

// ============================================================================
// K3: u = G * (Wv2 @ vi); if useWd: out = vn_lrelu(Wd, u) else out = u
// warp-per-node
// ============================================================================
__global__ void k_gatevn(const float* __restrict__ vi, const float* __restrict__ G,
                         const float* __restrict__ Wv2, const float* __restrict__ Wd,
                         float* __restrict__ out, int n, int useWd) {
    __shared__ float Wt2[4096];
    __shared__ float WtD[4096];
    __shared__ float viS[8][192];
    __shared__ float uS[8][192];
    int tid = threadIdx.x, w = tid >> 5, lane = tid & 31;
    load_wt_transposed(Wv2, Wt2, tid, 256);
    if (useWd) load_wt_transposed(Wd, WtD, tid, 256);
    __syncthreads();

    int node = blockIdx.x * 8 + w;
    if (node >= n) return;

    const float* vv = vi + (size_t)node * 192;
    for (int i = lane; i < 192; i += 32) viS[w][i] = vv[i];
    __syncwarp();

    float u0[3] = {0,0,0}, u1[3] = {0,0,0};
#pragma unroll 8
    for (int c = 0; c < 64; c++) {
        float v0 = viS[w][c*3+0], v1 = viS[w][c*3+1], v2 = viS[w][c*3+2];
        float w0 = Wt2[c*64 + lane], w1 = Wt2[c*64 + lane + 32];
        u0[0] = fmaf(w0, v0, u0[0]); u0[1] = fmaf(w0, v1, u0[1]); u0[2] = fmaf(w0, v2, u0[2]);
        u1[0] = fmaf(w1, v0, u1[0]); u1[1] = fmaf(w1, v1, u1[1]); u1[2] = fmaf(w1, v2, u1[2]);
    }
    float g0 = G[(size_t)node * 64 + lane];
    float g1 = G[(size_t)node * 64 + lane + 32];
#pragma unroll
    for (int d = 0; d < 3; d++) { u0[d] *= g0; u1[d] *= g1; }

    float* op = out + (size_t)node * 192;
    if (!useWd) {
#pragma unroll
        for (int d = 0; d < 3; d++) {
            op[lane*3 + d]      = u0[d];
            op[(lane+32)*3 + d] = u1[d];
        }
        return;
    }
#pragma unroll
    for (int d = 0; d < 3; d++) {
        uS[w][lane*3 + d]      = u0[d];
        uS[w][(lane+32)*3 + d] = u1[d];
    }
    __syncwarp();

    float d0[3] = {0,0,0}, d1[3] = {0,0,0};
#pragma unroll 8
    for (int c = 0; c < 64; c++) {
        float v0 = uS[w][c*3+0], v1 = uS[w][c*3+1], v2 = uS[w][c*3+2];
        float w0 = WtD[c*64 + lane], w1 = WtD[c*64 + lane + 32];
        d0[0] = fmaf(w0, v0, d0[0]); d0[1] = fmaf(w0, v1, d0[1]); d0[2] = fmaf(w0, v2, d0[2]);
        d1[0] = fmaf(w1, v0, d1[0]); d1[1] = fmaf(w1, v1, d1[1]); d1[2] = fmaf(w1, v2, d1[2]);
    }
    // vn_lrelu on (u, d) per channel
    {
        float dot = u0[0]*d0[0] + u0[1]*d0[1] + u0[2]*d0[2];
        float dsq = d0[0]*d0[0] + d0[1]*d0[1] + d0[2]*d0[2];
        float s   = dot / (dsq + EPSF);
#pragma unroll
        for (int d = 0; d < 3; d++) {
            float x = u0[d];
            float proj = x - s * d0[d];
            float r = (dot >= 0.f) ? x : (SLOPEF * x + (1.f - SLOPEF) * proj);
            op[lane*3 + d] = r;
        }
    }
    {
        float dot = u1[0]*d1[0] + u1[1]*d1[1] + u1[2]*d1[2];
        float dsq = d1[0]*d1[0] + d1[1]*d1[1] + d1[2]*d1[2];
        float s   = dot / (dsq + EPSF);
#pragma unroll
        for (int d = 0; d < 3; d++) {
            float x = u1[d];
            float proj = x - s * d1[d];
            float r = (dot >= 0.f) ? x : (SLOPEF * x + (1.f - SLOPEF) * proj);
            op[(lane+32)*3 + d] = r;
        }
    }
}

// ============================================================================
// K4: att[n] = Ws0[0:64] . |a2Wv1 @ v|  +  Ws0[64:320] . lrelu(Sa[n])
// warp-per-node
// ============================================================================
__global__ void k_att(const float* __restrict__ v, const float* __restrict__ Wv1,
                      const float* __restrict__ Ws, const float* __restrict__ S,
                      float* __restrict__ att, int n) {
    __shared__ float Wt[4096];
    __shared__ float wsS[320];
    __shared__ float vS[8][192];
    int tid = threadIdx.x, w = tid >> 5, lane = tid & 31;
    load_wt_transposed(Wv1, Wt, tid, 256);
    for (int i = tid; i < 320; i += 256) wsS[i] = Ws[i];
    __syncthreads();

    int node = blockIdx.x * 8 + w;
    if (node >= n) return;

    const float* vv = v + (size_t)node * 192;
    for (int i = lane; i < 192; i += 32) vS[w][i] = vv[i];
    __syncwarp();

    float a0[3] = {0,0,0}, a1[3] = {0,0,0};
#pragma unroll 8
    for (int c = 0; c < 64; c++) {
        float v0 = vS[w][c*3+0], v1 = vS[w][c*3+1], v2 = vS[w][c*3+2];
        float w0 = Wt[c*64 + lane], w1 = Wt[c*64 + lane + 32];
        a0[0] = fmaf(w0, v0, a0[0]); a0[1] = fmaf(w0, v1, a0[1]); a0[2] = fmaf(w0, v2, a0[2]);
        a1[0] = fmaf(w1, v0, a1[0]); a1[1] = fmaf(w1, v1, a1[1]); a1[2] = fmaf(w1, v2, a1[2]);
    }
    float n0 = sqrtf(a0[0]*a0[0] + a0[1]*a0[1] + a0[2]*a0[2]);
    float n1 = sqrtf(a1[0]*a1[0] + a1[1]*a1[1] + a1[2]*a1[2]);
    float p = wsS[lane] * n0 + wsS[lane + 32] * n1;
    const float* s = S + (size_t)node * 256;
    for (int k = lane; k < 256; k += 32) {
        float sv = s[k];
        sv = (sv >= 0.f) ? sv : SLOPEF * sv;
        p = fmaf(wsS[64 + k], sv, p);
    }
#pragma unroll
    for (int o = 16; o > 0; o >>= 1) p += __shfl_down_sync(0xffffffff, p, o);
    if (lane == 0) att[node] = p;
}

// ============================================================================
// K5: vi2 = n2Wv1 @ v ; X2 = [|vi2|, lrelu(Sn)]
// ============================================================================
__global__ void k_vn3n(const float* __restrict__ v, const float* __restrict__ Wv1,
                       const float* __restrict__ S,
                       float* __restrict__ vi2, float* __restrict__ X2, int n) {
    __shared__ float Wt[4096];
    __shared__ float vS[8][192];
    int tid = threadIdx.x, w = tid >> 5, lane = tid & 31;
    load_wt_transposed(Wv1, Wt, tid, 256);
    __syncthreads();

    int node = blockIdx.x * 8 + w;
    if (node >= n) return;

    const float* vv = v + (size_t)node * 192;
    for (int i = lane; i < 192; i += 32) vS[w][i] = vv[i];

    float* x2 = X2 + (size_t)node * 320;
    const float* s = S + (size_t)node * 256;
    for (int k = lane; k < 256; k += 32) {
        float sv = s[k];
        x2[64 + k] = (sv >= 0.f) ? sv : SLOPEF * sv;
    }
    __syncwarp();

    float a0[3] = {0,0,0}, a1[3] = {0,0,0};
#pragma unroll 8
    for (int c = 0; c < 64; c++) {
        float v0 = vS[w][c*3+0], v1 = vS[w][c*3+1], v2 = vS[w][c*3+2];
        float w0 = Wt[c*64 + lane], w1 = Wt[c*64 + lane + 32];
        a0[0] = fmaf(w0, v0, a0[0]); a0[1] = fmaf(w0, v1, a0[1]); a0[2] = fmaf(w0, v2, a0[2]);
        a1[0] = fmaf(w1, v0, a1[0]); a1[1] = fmaf(w1, v1, a1[1]); a1[2] = fmaf(w1, v2, a1[2]);
    }
    float* vp = vi2 + (size_t)node * 192;
#pragma unroll
    for (int d = 0; d < 3; d++) {
        vp[lane*3 + d]      = a0[d];
        vp[(lane+32)*3 + d] = a1[d];
    }
    x2[lane]      = sqrtf(a0[0]*a0[0] + a0[1]*a0[1] + a0[2]*a0[2]);
    x2[lane + 32] = sqrtf(a1[0]*a1[0] + a1[1]*a1[1] + a1[2]*a1[2]);
}

// ============================================================================
// segment offsets (batch_id sorted): start[b] = lower_bound(bid, b), start[B]=n
// ============================================================================
__global__ void k_segstart(const int* __restrict__ bid, int n, int B, int* __restrict__ start) {
    int b = blockIdx.x * blockDim.x + threadIdx.x;
    if (b > B) return;
    int lo = 0, hi = n;
    while (lo < hi) {
        int mid = (lo + hi) >> 1;
        if (bid[mid] < b) lo = mid + 1; else hi = mid;
    }
    start[b] = lo;
}

// ============================================================================
// segment softmax: one block per segment
// ============================================================================
__global__ void k_softmax(const float* __restrict__ att, const int* __restrict__ start,
                          float* __restrict__ w) {
    int b = blockIdx.x;
    int s = start[b], e = start[b + 1];
    if (s >= e) return;
    __shared__ float red[256];
    int tid = threadIdx.x;
    float m = -INFINITY;
    for (int i = s + tid; i < e; i += 256) m = fmaxf(m, att[i]);
    red[tid] = m; __syncthreads();
    for (int o = 128; o > 0; o >>= 1) {
        if (tid < o) red[tid] = fmaxf(red[tid], red[tid + o]);
        __syncthreads();
    }
    m = red[0]; __syncthreads();
    float zs = 0.f;
    for (int i = s + tid; i < e; i += 256) zs += __expf(att[i] - m);
    red[tid] = zs; __syncthreads();
    for (int o = 128; o > 0; o >>= 1) {
        if (tid < o) red[tid] += red[tid + o];
        __syncthreads();
    }
    float z = red[0];
    float inv = 1.f / z;
    for (int i = s + tid; i < e; i += 256) w[i] = __expf(att[i] - m) * inv;
}

// ============================================================================
// weighted segment reduce: one block (256 thr) per segment
// out layout: [B,256] feat | [B,64,3] vec | [B,3] pos
// ============================================================================
__global__ void k_reduce(const float* __restrict__ w, const float* __restrict__ fs,
                         const float* __restrict__ fv, const float* __restrict__ pos,
                         const int* __restrict__ start, int B, float* __restrict__ out) {
    int b = blockIdx.x, j = threadIdx.x;
    int s = start[b], e = start[b + 1];
    float a256 = 0.f, a192 = 0.f, a3 = 0.f;
    for (int i = s; i < e; i++) {
        float wi = w[i];
        a256 = fmaf(wi, fs[(size_t)i * 256 + j], a256);
        if (j < 192) a192 = fmaf(wi, fv[(size_t)i * 192 + j], a192);
        if (j < 3)   a3   = fmaf(wi, pos[(size_t)i * 3 + j], a3);
    }
    out[(size_t)b * 256 + j] = a256;
    if (j < 192) out[(size_t)B * 256 + (size_t)b * 192 + j] = a192;
    if (j < 3)   out[(size_t)B * 256 + (size_t)B * 192 + (size_t)b * 3 + j] = a3;
}

// ============================================================================
// launch
// ============================================================================
extern "C" void kernel_launch(void* const* d_in, const int* in_sizes, int n_in,
                              void* d_out, int out_size) {
    const float* h_sca = (const float*)d_in[0];
    const float* h_vec = (const float*)d_in[1];
    const float* pos   = (const float*)d_in[2];
    const float* te    = (const float*)d_in[3];
    const float* a1Wv1 = (const float*)d_in[4];
    const float* a1Wv2 = (const float*)d_in[5];
    const float* a1Ws  = (const float*)d_in[6];
    const float* a1Wg  = (const float*)d_in[7];
    const float* a1bg  = (const float*)d_in[8];
    const float* a1Wd  = (const float*)d_in[9];
    const float* a2Wv1 = (const float*)d_in[10];
    const float* a2Ws  = (const float*)d_in[12];
    const float* n1Wv1 = (const float*)d_in[15];
    const float* n1Wv2 = (const float*)d_in[16];
    const float* n1Ws  = (const float*)d_in[17];
    const float* n1Wg  = (const float*)d_in[18];
    const float* n1bg  = (const float*)d_in[19];
    const float* n1Wd  = (const float*)d_in[20];
    const float* n2Wv1 = (const float*)d_in[21];
    const float* n2Wv2 = (const float*)d_in[22];
    const float* n2Ws  = (const float*)d_in[23];
    const float* n2Wg  = (const float*)d_in[24];
    const float* n2bg  = (const float*)d_in[25];
    const int*   tptr  = (const int*)d_in[26];
    const int*   bid   = (const int*)d_in[27];

    int n = in_sizes[0] / 256;
    int B = out_size / 451;   // 256 + 192 + 3

    float *viA, *viN, *Xa, *Xn, *Sa, *Sn, *Ga, *Gn, *va, *vnn, *att, *w;
    int* segs;
    cudaGetSymbolAddress((void**)&viA, g_viA);
    cudaGetSymbolAddress((void**)&viN, g_viN);
    cudaGetSymbolAddress((void**)&Xa,  g_Xa);
    cudaGetSymbolAddress((void**)&Xn,  g_Xn);
    cudaGetSymbolAddress((void**)&Sa,  g_Sa);
    cudaGetSymbolAddress((void**)&Sn,  g_Sn);
    cudaGetSymbolAddress((void**)&Ga,  g_Ga);
    cudaGetSymbolAddress((void**)&Gn,  g_Gn);
    cudaGetSymbolAddress((void**)&va,  g_va);
    cudaGetSymbolAddress((void**)&vnn, g_vn);
    cudaGetSymbolAddress((void**)&att, g_att);
    cudaGetSymbolAddress((void**)&w,   g_w);
    cudaGetSymbolAddress((void**)&segs, g_segstart);

    int nb8 = (n + 7) / 8;
    dim3 gS((n + 63) / 64, 4);   // Nc=256
    dim3 gG((n + 63) / 64, 1);   // Nc=64

    // front: vi + X for both branches
    k_front<<<nb8, 256>>>(h_sca, h_vec, te, tptr, a1Wv1, n1Wv1, viA, viN, Xa, Xn, n);
    // out_sca GEMMs
    gemm_nt<0><<<gS, 256>>>(Xa, a1Ws, nullptr, Sa, n, 256, 320);
    gemm_nt<0><<<gS, 256>>>(Xn, n1Ws, nullptr, Sn, n, 256, 320);
    // gates
    gemm_nt<1><<<gG, 256>>>(Sa, a1Wg, a1bg, Ga, n, 64, 256);
    gemm_nt<1><<<gG, 256>>>(Sn, n1Wg, n1bg, Gn, n, 64, 256);
    // gated Wv2 + vn_lrelu
    k_gatevn<<<nb8, 256>>>(viA, Ga, a1Wv2, a1Wd, va,  n, 1);
    k_gatevn<<<nb8, 256>>>(viN, Gn, n1Wv2, n1Wd, vnn, n, 1);
    // attention scalar
    k_att<<<nb8, 256>>>(va, a2Wv1, a2Ws, Sa, att, n);
    // net2 front (reuse viA as vi2, Xa as X2)
    k_vn3n<<<nb8, 256>>>(vnn, n2Wv1, Sn, viA, Xa, n);
    // fs (reuse Sa), gate2 (reuse Ga), fv (reuse va)
    gemm_nt<0><<<gS, 256>>>(Xa, n2Ws, nullptr, Sa, n, 256, 320);
    gemm_nt<1><<<gG, 256>>>(Sa, n2Wg, n2bg, Ga, n, 64, 256);
    k_gatevn<<<nb8, 256>>>(viA, Ga, n2Wv2, nullptr, va, n, 0);
    // segment softmax + weighted reduce
    k_segstart<<<(B + 1 + 255) / 256, 256>>>(bid, n, B, segs);
    k_softmax<<<B, 256>>>(att, segs, w);
    k_reduce<<<B, 256>>>(w, Sa, va, pos, segs, B, (float*)d_out);
}

// round 5
// speedup vs baseline: 1.7000x; 1.6998x over previous
#include <cuda_runtime.h>
#include <cuda_bf16.h>
#include <math.h>
#include <stdint.h>

typedef __nv_bfloat16 bf16;

#define MAXN   120000
#define SLOPEF 0.01f
#define EPSF   1e-6f
#define PVMAX  (3*MAXN*64)

// ---------------- static device scratch ----------------
__device__ __align__(16) bf16  g_vecS[2*PVMAX];
__device__ __align__(16) bf16  g_viAs[2*PVMAX];
__device__ __align__(16) bf16  g_viNs[2*PVMAX];
__device__ __align__(16) bf16  g_uas [2*PVMAX];
__device__ __align__(16) bf16  g_uns [2*PVMAX];
__device__ __align__(16) bf16  g_vas [2*PVMAX];
__device__ __align__(16) bf16  g_vns [2*PVMAX];
__device__ __align__(16) bf16  g_Xa  [2*MAXN*320];
__device__ __align__(16) bf16  g_Xn  [2*MAXN*320];
__device__ __align__(16) bf16  g_Sas [2*MAXN*256];
__device__ __align__(16) bf16  g_Sns [2*MAXN*256];
__device__ __align__(16) bf16  g_Baug[1048576];
__device__ float g_sca [MAXN*256];
__device__ float g_viAf[PVMAX];
__device__ float g_viNf[PVMAX];
__device__ float g_uaf [PVMAX];
__device__ float g_unf [PVMAX];
__device__ float g_daf [PVMAX];
__device__ float g_dnf [PVMAX];
__device__ float g_Saf [MAXN*256];
__device__ float g_Snf [MAXN*256];
__device__ float g_Ga  [MAXN*64];
__device__ float g_Gn  [MAXN*64];
__device__ float g_att [MAXN];
__device__ float g_w   [MAXN];
__device__ int   g_seg [4100];

// ---------------- helpers ----------------
__device__ __forceinline__ uint32_t smem_u32(const void* p) {
    return (uint32_t)__cvta_generic_to_shared(p);
}
__device__ __forceinline__ void split2(float x, bf16& h, bf16& l) {
    h = __float2bfloat16(x);
    l = __float2bfloat16(x - __bfloat162float(h));
}

#define MMA16816(d, a, b)                                                     \
    asm volatile("mma.sync.aligned.m16n8k16.row.col.f32.bf16.bf16.f32 "      \
        "{%0,%1,%2,%3}, {%4,%5,%6,%7}, {%8,%9}, {%0,%1,%2,%3};"              \
        : "+f"((d)[0]), "+f"((d)[1]), "+f"((d)[2]), "+f"((d)[3])             \
        : "r"((a)[0]), "r"((a)[1]), "r"((a)[2]), "r"((a)[3]),                \
          "r"((b)[0]), "r"((b)[1]))

#define LDSM_X4(r0, r1, r2, r3, addr)                                        \
    asm volatile("ldmatrix.sync.aligned.m8n8.x4.shared.b16 {%0,%1,%2,%3}, [%4];" \
        : "=r"(r0), "=r"(r1), "=r"(r2), "=r"(r3) : "r"(addr))

#define CP_ASYNC16(sa, ga)                                                   \
    asm volatile("cp.async.cg.shared.global [%0], [%1], 16;" :: "r"(sa), "l"(ga))
#define CP_ASYNC16_P(sa, ga, p)                                              \
    asm volatile("cp.async.cg.shared.global [%0], [%1], 16, %2;" :: "r"(sa), "l"(ga), "r"(p))
#define CP_COMMIT() asm volatile("cp.async.commit_group;")
#define CP_WAIT1()  asm volatile("cp.async.wait_group 1;")
#define CP_WAIT0()  asm volatile("cp.async.wait_group 0;")

// ---------------------------------------------------------------------------
// HMMA GEMM: C[M,NC] = epi( Asplit[M,K] @ Baug[NC,3K]^T )
// Tile: 128(M) x 64(N) x 32(K).  8 warps = 4(M) x 2(N), warp tile 32x32.
// A thirds [hi|hi|lo], Baug rows [hi|lo|hi] prepacked.
// ---------------------------------------------------------------------------
struct GSet {
    const bf16* Ahi; const bf16* Alo;
    const bf16* B;
    float* Cf; bf16* Chi; bf16* Clo;
    const float* bias; const float* gate;
    int act;
};

__global__ void __launch_bounds__(256)
gemm_bf16(GSet s0, GSet s1, int M, int K, int NC, int Nn) {
    __shared__ bf16 As[2][128][40];
    __shared__ bf16 Bs[2][64][40];

    const int tid = threadIdx.x;
    const int lane = tid & 31, wid = tid >> 5;
    const int wm = wid >> 1, wn = wid & 1;
    const GSet S = (blockIdx.y == 0) ? s0 : s1;
    const int m0 = blockIdx.x * 128;
    const int n0 = blockIdx.z * 64;
    const int KC = K >> 5;               // 32-wide chunks per third
    const int nch = 3 * KC;
    const size_t K3 = (size_t)3 * K;

    float acc[2][4][4];
#pragma unroll
    for (int i = 0; i < 2; i++)
#pragma unroll
        for (int j = 0; j < 4; j++)
#pragma unroll
            for (int k = 0; k < 4; k++) acc[i][j][k] = 0.f;

    // -------- stage loader --------
    auto load_stage = [&](int c, int buf) {
        const bf16* Ab = (c < 2 * KC) ? S.Ahi : S.Alo;
        int third = c / KC;
        int kof = (c - third * KC) * 32;
#pragma unroll
        for (int it = 0; it < 2; it++) {          // A: 512 x 16B
            int i = tid + it * 256;
            int r = i >> 2, sg = i & 3;
            int m = m0 + r;
            uint32_t sa = smem_u32(&As[buf][r][sg * 8]);
            const bf16* ga = Ab + ((m < M) ? ((size_t)m * K + kof + sg * 8) : 0);
            int p = (m < M) ? 16 : 0;
            CP_ASYNC16_P(sa, ga, p);
        }
        {                                          // B: 256 x 16B
            int r = tid >> 2, sg = tid & 3;
            uint32_t sa = smem_u32(&Bs[buf][r][sg * 8]);
            const bf16* ga = S.B + (size_t)(n0 + r) * K3 + c * 32 + sg * 8;
            CP_ASYNC16(sa, ga);
        }
        CP_COMMIT();
    };

    load_stage(0, 0);
    for (int c = 0; c < nch; c++) {
        int buf = c & 1;
        if (c + 1 < nch) { load_stage(c + 1, buf ^ 1); CP_WAIT1(); }
        else             { CP_WAIT0(); }
        __syncthreads();
#pragma unroll
        for (int kk = 0; kk < 2; kk++) {
            const int k16 = kk * 16;
            uint32_t a[2][4];
#pragma unroll
            for (int mt = 0; mt < 2; mt++) {
                uint32_t ad = smem_u32(&As[buf][wm * 32 + mt * 16 + (lane & 15)]
                                          [k16 + (lane >> 4) * 8]);
                LDSM_X4(a[mt][0], a[mt][1], a[mt][2], a[mt][3], ad);
            }
            uint32_t b[4][2];
#pragma unroll
            for (int half = 0; half < 2; half++) {
                int g = lane >> 3, r = lane & 7;
                int nt = (g >> 1);
                int ko = (g & 1) * 8;
                uint32_t ad = smem_u32(&Bs[buf][wn * 32 + half * 16 + nt * 8 + r][k16 + ko]);
                uint32_t r0, r1, r2, r3;
                LDSM_X4(r0, r1, r2, r3, ad);
                b[half * 2 + 0][0] = r0; b[half * 2 + 0][1] = r1;
                b[half * 2 + 1][0] = r2; b[half * 2 + 1][1] = r3;
            }
#pragma unroll
            for (int mt = 0; mt < 2; mt++)
#pragma unroll
                for (int nt = 0; nt < 4; nt++)
                    MMA16816(acc[mt][nt], a[mt], b[nt]);
        }
        __syncthreads();
    }

    // -------- epilogue --------
#pragma unroll
    for (int mt = 0; mt < 2; mt++) {
#pragma unroll
        for (int h = 0; h < 2; h++) {
            int m = m0 + wm * 32 + mt * 16 + (lane >> 2) + h * 8;
            if (m >= M) continue;
            int node = m % Nn;
#pragma unroll
            for (int nt = 0; nt < 4; nt++) {
                int col = n0 + wn * 32 + nt * 8 + (lane & 3) * 2;
#pragma unroll
                for (int e = 0; e < 2; e++) {
                    float v = acc[mt][nt][h * 2 + e];
                    int cc = col + e;
                    if (S.act) v = 1.f / (1.f + __expf(-(v + S.bias[cc])));
                    if (S.gate) v *= S.gate[(size_t)node * 64 + cc];
                    size_t o = (size_t)m * NC + cc;
                    if (S.Cf) S.Cf[o] = v;
                    if (S.Chi) { bf16 hh, ll; split2(v, hh, ll); S.Chi[o] = hh; S.Clo[o] = ll; }
                }
            }
        }
    }
}

// ---------------------------------------------------------------------------
// weight prepack: W(nc,k) fp32 -> Baug(nc,3k) bf16 rows [hi|lo|hi]
// ---------------------------------------------------------------------------
struct PPk { const float* w; bf16* o; int nc; int k; };
struct PPargs { PPk e[15]; };
__global__ void k_prepack(PPargs pa) {
    PPk p = pa.e[blockIdx.y];
    int tot = p.nc * p.k;
    for (int i = blockIdx.x * 256 + threadIdx.x; i < tot; i += gridDim.x * 256) {
        float x = p.w[i];
        bf16 h, l; split2(x, h, l);
        int r = i / p.k, kk = i - r * p.k;
        bf16* row = p.o + (size_t)r * 3 * p.k;
        row[kk] = h; row[p.k + kk] = l; row[2 * p.k + kk] = h;
    }
}

// ---------------------------------------------------------------------------
// elementwise stages
// ---------------------------------------------------------------------------
__global__ void k_prep(const float* __restrict__ h_sca, const float* __restrict__ h_vec,
                       const float* __restrict__ te, const int* __restrict__ tptr,
                       float* __restrict__ sca, bf16* __restrict__ vhi, int Nn) {
    size_t PV = (size_t)3 * Nn * 64;
    bf16* vlo = vhi + PV;
    int t = *tptr;
    int i = blockIdx.x * 256 + threadIdx.x;
    if (i >= Nn * 320) return;
    if (i < Nn * 256) {
        sca[i] = h_sca[i] + te[(size_t)t * 256 + (i & 255)];
    } else {
        int j = i - Nn * 256;
        int nrow = j >> 6, cc = j & 63;
#pragma unroll
        for (int d = 0; d < 3; d++) {
            float x = h_vec[(size_t)nrow * 192 + cc * 3 + d];
            bf16 h, l; split2(x, h, l);
            size_t o = (size_t)d * Nn * 64 + (size_t)nrow * 64 + cc;
            vhi[o] = h; vlo[o] = l;
        }
    }
}

__global__ void k_buildX(const float* __restrict__ viA, const float* __restrict__ viN,
                         const float* __restrict__ sca, bf16* __restrict__ XaH,
                         bf16* __restrict__ XnH, int Nn) {
    const float* vi = blockIdx.y ? viN : viA;
    bf16* Xh = blockIdx.y ? XnH : XaH;
    bf16* Xl = Xh + (size_t)Nn * 320;
    int i = blockIdx.x * 256 + threadIdx.x;
    if (i >= Nn * 320) return;
    int nrow = i / 320, col = i - nrow * 320;
    float x;
    if (col < 64) {
        size_t p = (size_t)nrow * 64 + col, P = (size_t)Nn * 64;
        float a = vi[p], b = vi[p + P], c2 = vi[p + 2 * P];
        x = sqrtf(a * a + b * b + c2 * c2);
    } else x = sca[(size_t)nrow * 256 + col - 64];
    bf16 h, l; split2(x, h, l);
    Xh[i] = h; Xl[i] = l;
}

__global__ void k_vnlrelu(const float* __restrict__ ua, const float* __restrict__ da,
                          const float* __restrict__ un, const float* __restrict__ dn,
                          bf16* __restrict__ vaS, bf16* __restrict__ vnS, int Nn) {
    const float* u  = blockIdx.y ? un : ua;
    const float* dd = blockIdx.y ? dn : da;
    bf16* vh = blockIdx.y ? vnS : vaS;
    size_t P = (size_t)Nn * 64;
    bf16* vl = vh + 3 * P;
    int i = blockIdx.x * 256 + threadIdx.x;
    if (i >= Nn * 64) return;
    float u0 = u[i], u1 = u[i + P], u2 = u[i + 2 * P];
    float d0 = dd[i], d1 = dd[i + P], d2 = dd[i + 2 * P];
    float dot = u0 * d0 + u1 * d1 + u2 * d2;
    float dsq = d0 * d0 + d1 * d1 + d2 * d2;
    float s = dot / (dsq + EPSF);
    float r0, r1, r2;
    if (dot >= 0.f) { r0 = u0; r1 = u1; r2 = u2; }
    else {
        r0 = SLOPEF * u0 + (1.f - SLOPEF) * (u0 - s * d0);
        r1 = SLOPEF * u1 + (1.f - SLOPEF) * (u1 - s * d1);
        r2 = SLOPEF * u2 + (1.f - SLOPEF) * (u2 - s * d2);
    }
    bf16 h, l;
    split2(r0, h, l); vh[i] = h;           vl[i] = l;
    split2(r1, h, l); vh[i + P] = h;       vl[i + P] = l;
    split2(r2, h, l); vh[i + 2 * P] = h;   vl[i + 2 * P] = l;
}

__global__ void k_buildX2(const float* __restrict__ vi2n, const float* __restrict__ Sn,
                          bf16* __restrict__ Xh, int Nn) {
    bf16* Xl = Xh + (size_t)Nn * 320;
    int i = blockIdx.x * 256 + threadIdx.x;
    if (i >= Nn * 320) return;
    int nrow = i / 320, col = i - nrow * 320;
    float x;
    if (col < 64) {
        size_t p = (size_t)nrow * 64 + col, P = (size_t)Nn * 64;
        float a = vi2n[p], b = vi2n[p + P], c2 = vi2n[p + 2 * P];
        x = sqrtf(a * a + b * b + c2 * c2);
    } else {
        x = Sn[(size_t)nrow * 256 + col - 64];
        x = (x >= 0.f) ? x : SLOPEF * x;
    }
    bf16 h, l; split2(x, h, l);
    Xh[i] = h; Xl[i] = l;
}

__global__ void k_att(const float* __restrict__ vi2a, const float* __restrict__ Sa,
                      const float* __restrict__ Ws, float* __restrict__ att, int Nn) {
    __shared__ float ws[320];
    int tid = threadIdx.x, w = tid >> 5, lane = tid & 31;
    for (int i = tid; i < 320; i += 256) ws[i] = Ws[i];
    __syncthreads();
    int node = blockIdx.x * 8 + w;
    if (node >= Nn) return;
    size_t P = (size_t)Nn * 64;
    float p = 0.f;
    for (int c = lane; c < 64; c += 32) {
        size_t q = (size_t)node * 64 + c;
        float a = vi2a[q], b = vi2a[q + P], d = vi2a[q + 2 * P];
        p = fmaf(ws[c], sqrtf(a * a + b * b + d * d), p);
    }
    const float* s = Sa + (size_t)node * 256;
    for (int k = lane; k < 256; k += 32) {
        float sv = s[k];
        sv = (sv >= 0.f) ? sv : SLOPEF * sv;
        p = fmaf(ws[64 + k], sv, p);
    }
#pragma unroll
    for (int o = 16; o > 0; o >>= 1) p += __shfl_down_sync(0xffffffff, p, o);
    if (lane == 0) att[node] = p;
}

__global__ void k_segstart(const int* __restrict__ bid, int n, int B, int* __restrict__ start) {
    int b = blockIdx.x * blockDim.x + threadIdx.x;
    if (b > B) return;
    int lo = 0, hi = n;
    while (lo < hi) { int mid = (lo + hi) >> 1; if (bid[mid] < b) lo = mid + 1; else hi = mid; }
    start[b] = lo;
}

__global__ void k_softmax(const float* __restrict__ att, const int* __restrict__ start,
                          float* __restrict__ w) {
    int b = blockIdx.x;
    int s = start[b], e = start[b + 1];
    if (s >= e) return;
    __shared__ float red[256];
    int tid = threadIdx.x;
    float m = -INFINITY;
    for (int i = s + tid; i < e; i += 256) m = fmaxf(m, att[i]);
    red[tid] = m; __syncthreads();
    for (int o = 128; o > 0; o >>= 1) { if (tid < o) red[tid] = fmaxf(red[tid], red[tid + o]); __syncthreads(); }
    m = red[0]; __syncthreads();
    float zs = 0.f;
    for (int i = s + tid; i < e; i += 256) zs += __expf(att[i] - m);
    red[tid] = zs; __syncthreads();
    for (int o = 128; o > 0; o >>= 1) { if (tid < o) red[tid] += red[tid + o]; __syncthreads(); }
    float inv = 1.f / red[0];
    for (int i = s + tid; i < e; i += 256) w[i] = __expf(att[i] - m) * inv;
}

// fv in planes [d][node][64]
__global__ void k_reduce(const float* __restrict__ w, const float* __restrict__ fs,
                         const float* __restrict__ fv, const float* __restrict__ pos,
                         const int* __restrict__ start, int B, int Nn, float* __restrict__ out) {
    int b = blockIdx.x, j = threadIdx.x;
    int s = start[b], e = start[b + 1];
    size_t P = (size_t)Nn * 64;
    int c = j / 3, d = j - c * 3;
    float a256 = 0.f, a192 = 0.f, a3 = 0.f;
    for (int i = s; i < e; i++) {
        float wi = w[i];
        a256 = fmaf(wi, fs[(size_t)i * 256 + j], a256);
        if (j < 192) a192 = fmaf(wi, fv[(size_t)d * P + (size_t)i * 64 + c], a192);
        if (j < 3)   a3   = fmaf(wi, pos[(size_t)i * 3 + j], a3);
    }
    out[(size_t)b * 256 + j] = a256;
    if (j < 192) out[(size_t)B * 256 + (size_t)b * 192 + j] = a192;
    if (j < 3)   out[(size_t)B * 256 + (size_t)B * 192 + (size_t)b * 3 + j] = a3;
}

// ---------------------------------------------------------------------------
extern "C" void kernel_launch(void* const* d_in, const int* in_sizes, int n_in,
                              void* d_out, int out_size) {
    const float* h_sca = (const float*)d_in[0];
    const float* h_vec = (const float*)d_in[1];
    const float* pos   = (const float*)d_in[2];
    const float* te    = (const float*)d_in[3];
    const float* W[26];
    for (int i = 4; i <= 25; i++) W[i] = (const float*)d_in[i];
    const int* tptr = (const int*)d_in[26];
    const int* bid  = (const int*)d_in[27];

    int n = in_sizes[0] / 256;
    int B = out_size / 451;

    bf16 *vecS, *viAs, *viNs, *uas, *uns, *vas, *vns, *Xa, *Xn, *Sas, *Sns, *Baug;
    float *sca, *viAf, *viNf, *uaf, *unf, *daf, *dnf, *Saf, *Snf, *Ga, *Gn, *att, *wgt;
    int* segs;
    cudaGetSymbolAddress((void**)&vecS, g_vecS);
    cudaGetSymbolAddress((void**)&viAs, g_viAs);
    cudaGetSymbolAddress((void**)&viNs, g_viNs);
    cudaGetSymbolAddress((void**)&uas,  g_uas);
    cudaGetSymbolAddress((void**)&uns,  g_uns);
    cudaGetSymbolAddress((void**)&vas,  g_vas);
    cudaGetSymbolAddress((void**)&vns,  g_vns);
    cudaGetSymbolAddress((void**)&Xa,   g_Xa);
    cudaGetSymbolAddress((void**)&Xn,   g_Xn);
    cudaGetSymbolAddress((void**)&Sas,  g_Sas);
    cudaGetSymbolAddress((void**)&Sns,  g_Sns);
    cudaGetSymbolAddress((void**)&Baug, g_Baug);
    cudaGetSymbolAddress((void**)&sca,  g_sca);
    cudaGetSymbolAddress((void**)&viAf, g_viAf);
    cudaGetSymbolAddress((void**)&viNf, g_viNf);
    cudaGetSymbolAddress((void**)&uaf,  g_uaf);
    cudaGetSymbolAddress((void**)&unf,  g_unf);
    cudaGetSymbolAddress((void**)&daf,  g_daf);
    cudaGetSymbolAddress((void**)&dnf,  g_dnf);
    cudaGetSymbolAddress((void**)&Saf,  g_Saf);
    cudaGetSymbolAddress((void**)&Snf,  g_Snf);
    cudaGetSymbolAddress((void**)&Ga,   g_Ga);
    cudaGetSymbolAddress((void**)&Gn,   g_Gn);
    cudaGetSymbolAddress((void**)&att,  g_att);
    cudaGetSymbolAddress((void**)&wgt,  g_w);
    cudaGetSymbolAddress((void**)&segs, g_seg);

    // prepack weights -> Baug  rows [hi|lo|hi]
    // NOTE: entry 14 is n2_Wv2 = d_in[22] (round-4 bug: was 25 = n2_bg)
    static const int widx[15] = {4,15, 6,17, 7,18, 5,16, 9,20, 10,21, 23,24,22};
    static const int wnc[15]  = {64,64, 256,256, 64,64, 64,64, 64,64, 64,64, 256,64,64};
    static const int wk[15]   = {64,64, 320,320, 256,256, 64,64, 64,64, 64,64, 320,256,64};
    PPargs pa;
    size_t boff[15]; size_t acc = 0;
    for (int i = 0; i < 15; i++) {
        boff[i] = acc;
        pa.e[i] = PPk{W[widx[i]], Baug + acc, wnc[i], wk[i]};
        acc += (size_t)wnc[i] * 3 * wk[i];
    }
    const bf16 *B_a1Wv1 = Baug + boff[0],  *B_n1Wv1 = Baug + boff[1];
    const bf16 *B_a1Ws  = Baug + boff[2],  *B_n1Ws  = Baug + boff[3];
    const bf16 *B_a1Wg  = Baug + boff[4],  *B_n1Wg  = Baug + boff[5];
    const bf16 *B_a1Wv2 = Baug + boff[6],  *B_n1Wv2 = Baug + boff[7];
    const bf16 *B_a1Wd  = Baug + boff[8],  *B_n1Wd  = Baug + boff[9];
    const bf16 *B_a2Wv1 = Baug + boff[10], *B_n2Wv1 = Baug + boff[11];
    const bf16 *B_n2Ws  = Baug + boff[12], *B_n2Wg  = Baug + boff[13];
    const bf16 *B_n2Wv2 = Baug + boff[14];

    size_t PV = (size_t)3 * n * 64;
    int M3 = 3 * n;
    int g128_3 = (M3 + 127) / 128;
    int g128_1 = (n + 127) / 128;

    auto GS = [](const bf16* ah, const bf16* al, const bf16* b, float* cf,
                 bf16* ch, bf16* cl, const float* bias, const float* gate, int act) {
        GSet g; g.Ahi = ah; g.Alo = al; g.B = b; g.Cf = cf; g.Chi = ch; g.Clo = cl;
        g.bias = bias; g.gate = gate; g.act = act; return g;
    };

    k_prepack<<<dim3(256, 15), 256>>>(pa);
    k_prep<<<(n * 320 + 255) / 256, 256>>>(h_sca, h_vec, te, tptr, sca, vecS, n);

    // vi = Wv1 @ vec  (att/net pair), planes M = 3n
    gemm_bf16<<<dim3(g128_3, 2, 1), 256>>>(
        GS(vecS, vecS + PV, B_a1Wv1, viAf, viAs, viAs + PV, nullptr, nullptr, 0),
        GS(vecS, vecS + PV, B_n1Wv1, viNf, viNs, viNs + PV, nullptr, nullptr, 0),
        M3, 64, 64, n);
    k_buildX<<<dim3((n * 320 + 255) / 256, 2), 256>>>(viAf, viNf, sca, Xa, Xn, n);

    // S = X @ Ws  (pair), NC=256
    gemm_bf16<<<dim3(g128_1, 2, 4), 256>>>(
        GS(Xa, Xa + (size_t)n * 320, B_a1Ws, Saf, Sas, Sas + (size_t)n * 256, nullptr, nullptr, 0),
        GS(Xn, Xn + (size_t)n * 320, B_n1Ws, Snf, Sns, Sns + (size_t)n * 256, nullptr, nullptr, 0),
        n, 320, 256, n);
    // gates (pair)
    gemm_bf16<<<dim3(g128_1, 2, 1), 256>>>(
        GS(Sas, Sas + (size_t)n * 256, B_a1Wg, Ga, nullptr, nullptr, W[8], nullptr, 1),
        GS(Sns, Sns + (size_t)n * 256, B_n1Wg, Gn, nullptr, nullptr, W[19], nullptr, 1),
        n, 256, 64, n);
    // u = gate * (Wv2 @ vi)  (pair)
    gemm_bf16<<<dim3(g128_3, 2, 1), 256>>>(
        GS(viAs, viAs + PV, B_a1Wv2, uaf, uas, uas + PV, nullptr, Ga, 0),
        GS(viNs, viNs + PV, B_n1Wv2, unf, uns, uns + PV, nullptr, Gn, 0),
        M3, 64, 64, n);
    // d = Wd @ u  (pair)
    gemm_bf16<<<dim3(g128_3, 2, 1), 256>>>(
        GS(uas, uas + PV, B_a1Wd, daf, nullptr, nullptr, nullptr, nullptr, 0),
        GS(uns, uns + PV, B_n1Wd, dnf, nullptr, nullptr, nullptr, nullptr, 0),
        M3, 64, 64, n);
    k_vnlrelu<<<dim3((n * 64 + 255) / 256, 2), 256>>>(uaf, daf, unf, dnf, vas, vns, n);

    // vi2 = Wv1' @ v  (pair): att -> uaf (fp32), net -> unf + split into viAs
    gemm_bf16<<<dim3(g128_3, 2, 1), 256>>>(
        GS(vas, vas + PV, B_a2Wv1, uaf, nullptr, nullptr, nullptr, nullptr, 0),
        GS(vns, vns + PV, B_n2Wv1, unf, viAs, viAs + PV, nullptr, nullptr, 0),
        M3, 64, 64, n);
    k_att<<<(n + 7) / 8, 256>>>(uaf, Saf, W[12], att, n);
    k_buildX2<<<(n * 320 + 255) / 256, 256>>>(unf, Snf, Xa, n);

    // fs = X2 @ n2Ws  (NC=256)
    {
        GSet g = GS(Xa, Xa + (size_t)n * 320, B_n2Ws, Saf, Sas, Sas + (size_t)n * 256, nullptr, nullptr, 0);
        gemm_bf16<<<dim3(g128_1, 1, 4), 256>>>(g, g, n, 320, 256, n);
    }
    // gate2
    {
        GSet g = GS(Sas, Sas + (size_t)n * 256, B_n2Wg, Ga, nullptr, nullptr, W[25], nullptr, 1);
        gemm_bf16<<<dim3(g128_1, 1, 1), 256>>>(g, g, n, 256, 64, n);
    }
    // fv = gate2 * (n2Wv2 @ vi2n)
    {
        GSet g = GS(viAs, viAs + PV, B_n2Wv2, daf, nullptr, nullptr, nullptr, Ga, 0);
        gemm_bf16<<<dim3(g128_3, 1, 1), 256>>>(g, g, M3, 64, 64, n);
    }

    k_segstart<<<(B + 1 + 255) / 256, 256>>>(bid, n, B, segs);
    k_softmax<<<B, 256>>>(att, segs, wgt);
    k_reduce<<<B, 256>>>(wgt, Saf, daf, pos, segs, B, n, (float*)d_out);
}

// round 6
// speedup vs baseline: 2.4990x; 1.4700x over previous
#include <cuda_runtime.h>
#include <cuda_bf16.h>
#include <math.h>
#include <stdint.h>

typedef __nv_bfloat16 bf16;
typedef __nv_bfloat162 bf162;

#define MAXN   120000
#define SLOPEF 0.01f
#define EPSF   1e-6f
#define PVMAX  (3*MAXN*64)

// ---------------- static device scratch (bf16 split pairs: [hi | lo]) -------
__device__ __align__(16) bf16  g_vecS[2*PVMAX];
__device__ __align__(16) bf16  g_viAs[2*PVMAX];
__device__ __align__(16) bf16  g_viNs[2*PVMAX];
__device__ __align__(16) bf16  g_uas [2*PVMAX];
__device__ __align__(16) bf16  g_uns [2*PVMAX];
__device__ __align__(16) bf16  g_das [2*PVMAX];
__device__ __align__(16) bf16  g_dns [2*PVMAX];
__device__ __align__(16) bf16  g_vas [2*PVMAX];
__device__ __align__(16) bf16  g_vns [2*PVMAX];
__device__ __align__(16) bf16  g_Xa  [2*MAXN*320];
__device__ __align__(16) bf16  g_Xn  [2*MAXN*320];
__device__ __align__(16) bf16  g_Sas [2*MAXN*256];
__device__ __align__(16) bf16  g_Sns [2*MAXN*256];
__device__ __align__(16) bf16  g_Baug[1048576];
__device__ float g_Ga  [MAXN*64];
__device__ float g_Gn  [MAXN*64];
__device__ float g_att [MAXN];
__device__ float g_w   [MAXN];
__device__ int   g_seg [4100];

// ---------------- helpers ----------------
__device__ __forceinline__ uint32_t smem_u32(const void* p) {
    return (uint32_t)__cvta_generic_to_shared(p);
}
__device__ __forceinline__ void split2(float x, bf16& h, bf16& l) {
    h = __float2bfloat16(x);
    l = __float2bfloat16(x - __bfloat162float(h));
}
__device__ __forceinline__ float join2(bf16 h, bf16 l) {
    return __bfloat162float(h) + __bfloat162float(l);
}

#define MMA16816(d, a, b)                                                     \
    asm volatile("mma.sync.aligned.m16n8k16.row.col.f32.bf16.bf16.f32 "      \
        "{%0,%1,%2,%3}, {%4,%5,%6,%7}, {%8,%9}, {%0,%1,%2,%3};"              \
        : "+f"((d)[0]), "+f"((d)[1]), "+f"((d)[2]), "+f"((d)[3])             \
        : "r"((a)[0]), "r"((a)[1]), "r"((a)[2]), "r"((a)[3]),                \
          "r"((b)[0]), "r"((b)[1]))

#define LDSM_X4(r0, r1, r2, r3, addr)                                        \
    asm volatile("ldmatrix.sync.aligned.m8n8.x4.shared.b16 {%0,%1,%2,%3}, [%4];" \
        : "=r"(r0), "=r"(r1), "=r"(r2), "=r"(r3) : "r"(addr))

#define CP_ASYNC16(sa, ga)                                                   \
    asm volatile("cp.async.cg.shared.global [%0], [%1], 16;" :: "r"(sa), "l"(ga))
#define CP_ASYNC16_P(sa, ga, p)                                              \
    asm volatile("cp.async.cg.shared.global [%0], [%1], 16, %2;" :: "r"(sa), "l"(ga), "r"(p))
#define CP_COMMIT() asm volatile("cp.async.commit_group;")
#define CP_WAIT1()  asm volatile("cp.async.wait_group 1;")
#define CP_WAIT0()  asm volatile("cp.async.wait_group 0;")

// ---------------------------------------------------------------------------
// HMMA GEMM:  C[M,NC] = epi( (Ahi+Alo)[M,K] @ (Bhi+Blo)[NC,K]^T )
// Baug rows prepacked [hi | lo] (2K wide).
// Stage schedule (2*KC stages): s<KC: load Ahi(s), MMA vs Bhi(s) and Blo(s);
//                               s>=KC: load Alo(s-KC), MMA vs Bhi(s-KC).
// Tile 128 x NC.  NC=64: 256 thr, 8 warps (4Mx2N).  NC=256: 512 thr, 16 (4x4).
// Output: split bf16 (Chi/Clo) or fp32 (Cf) with optional sigmoid+bias / gate.
// ---------------------------------------------------------------------------
struct GSet {
    const bf16* Ahi; const bf16* Alo;
    const bf16* B;
    float* Cf; bf16* Chi; bf16* Clo;
    const float* bias; const float* gate;
    int act;
};

template <int NC>
__global__ void __launch_bounds__(NC == 256 ? 512 : 256)
gemm_bf16(GSet s0, GSet s1, int M, int K, int Nn) {
    constexpr int NTH   = (NC == 256) ? 512 : 256;
    constexpr int NWN   = (NC == 256) ? 4 : 2;       // warps along N
    constexpr int WCOLS = NC / NWN;                  // 64 or 32
    constexpr int NT    = WCOLS / 8;                 // 8 or 4
    constexpr int A_ST  = 128 * 40;                  // elements per A stage
    constexpr int B_ST  = NC * 40;                   // elements per B sub-chunk

    extern __shared__ bf16 sm[];
    bf16* smA = sm;                                   // [2][128][40]
    bf16* smB = sm + 2 * A_ST;                        // [2][2][NC][40]

    const int tid = threadIdx.x;
    const int lane = tid & 31, wid = tid >> 5;
    const int wm = wid / NWN, wn = wid % NWN;
    const GSet S = (blockIdx.y == 0) ? s0 : s1;
    const int m0 = blockIdx.x * 128;
    const int KC = K >> 5;
    const int ST = 2 * KC;
    const size_t K2 = (size_t)2 * K;

    float acc[2][NT][4];
#pragma unroll
    for (int i = 0; i < 2; i++)
#pragma unroll
        for (int j = 0; j < NT; j++)
#pragma unroll
            for (int k = 0; k < 4; k++) acc[i][j][k] = 0.f;

    auto load_stage = [&](int s, int buf) {
        const bf16* Ab; int kof;
        if (s < KC) { Ab = S.Ahi; kof = s * 32; }
        else        { Ab = S.Alo; kof = (s - KC) * 32; }
        // A chunk: 128 rows x 32 cols = 512 x 16B
        for (int i = tid; i < 512; i += NTH) {
            int r = i >> 2, sg = i & 3;
            int m = m0 + r;
            uint32_t sa = smem_u32(smA + buf * A_ST + r * 40 + sg * 8);
            const bf16* ga = Ab + ((m < M) ? ((size_t)m * K + kof + sg * 8) : 0);
            CP_ASYNC16_P(sa, ga, (m < M) ? 16 : 0);
        }
        // B hi chunk
        int c0 = ((s < KC) ? s : (s - KC)) * 32;
        for (int i = tid; i < NC * 4; i += NTH) {
            int r = i >> 2, sg = i & 3;
            uint32_t sa = smem_u32(smB + (buf * 2 + 0) * B_ST + r * 40 + sg * 8);
            CP_ASYNC16(sa, S.B + (size_t)r * K2 + c0 + sg * 8);
        }
        // B lo chunk (hi-pass stages only)
        if (s < KC) {
            int c1 = K + s * 32;
            for (int i = tid; i < NC * 4; i += NTH) {
                int r = i >> 2, sg = i & 3;
                uint32_t sa = smem_u32(smB + (buf * 2 + 1) * B_ST + r * 40 + sg * 8);
                CP_ASYNC16(sa, S.B + (size_t)r * K2 + c1 + sg * 8);
            }
        }
        CP_COMMIT();
    };

    load_stage(0, 0);
    for (int s = 0; s < ST; s++) {
        int buf = s & 1;
        if (s + 1 < ST) { load_stage(s + 1, buf ^ 1); CP_WAIT1(); }
        else            { CP_WAIT0(); }
        __syncthreads();
        const bool dual = (s < KC);
#pragma unroll
        for (int kk = 0; kk < 2; kk++) {
            const int k16 = kk * 16;
            uint32_t a[2][4];
#pragma unroll
            for (int mt = 0; mt < 2; mt++) {
                uint32_t ad = smem_u32(smA + buf * A_ST
                                       + (wm * 32 + mt * 16 + (lane & 15)) * 40
                                       + k16 + (lane >> 4) * 8);
                LDSM_X4(a[mt][0], a[mt][1], a[mt][2], a[mt][3], ad);
            }
#pragma unroll
            for (int sub = 0; sub < 2; sub++) {
                if (sub == 1 && !dual) break;
                uint32_t b[NT][2];
#pragma unroll
                for (int half = 0; half < NT / 2; half++) {
                    int g = lane >> 3, r = lane & 7;
                    int nt8 = (g >> 1), ko = (g & 1) * 8;
                    uint32_t ad = smem_u32(smB + (buf * 2 + sub) * B_ST
                                           + (wn * WCOLS + half * 16 + nt8 * 8 + r) * 40
                                           + k16 + ko);
                    uint32_t r0, r1, r2, r3;
                    LDSM_X4(r0, r1, r2, r3, ad);
                    b[half * 2 + 0][0] = r0; b[half * 2 + 0][1] = r1;
                    b[half * 2 + 1][0] = r2; b[half * 2 + 1][1] = r3;
                }
#pragma unroll
                for (int mt = 0; mt < 2; mt++)
#pragma unroll
                    for (int nt = 0; nt < NT; nt++)
                        MMA16816(acc[mt][nt], a[mt], b[nt]);
            }
        }
        __syncthreads();
    }

    // -------- epilogue --------
#pragma unroll
    for (int mt = 0; mt < 2; mt++) {
#pragma unroll
        for (int h = 0; h < 2; h++) {
            int m = m0 + wm * 32 + mt * 16 + (lane >> 2) + h * 8;
            if (m >= M) continue;
            int node = m % Nn;
#pragma unroll
            for (int nt = 0; nt < NT; nt++) {
                int col = wn * WCOLS + nt * 8 + (lane & 3) * 2;
                float v0 = acc[mt][nt][h * 2 + 0];
                float v1 = acc[mt][nt][h * 2 + 1];
                if (S.act) {
                    v0 = 1.f / (1.f + __expf(-(v0 + S.bias[col])));
                    v1 = 1.f / (1.f + __expf(-(v1 + S.bias[col + 1])));
                }
                if (S.gate) {
                    v0 *= S.gate[(size_t)node * 64 + col];
                    v1 *= S.gate[(size_t)node * 64 + col + 1];
                }
                size_t o = (size_t)m * NC + col;
                if (S.Cf) {
                    *(float2*)(S.Cf + o) = make_float2(v0, v1);
                } else {
                    bf16 h0, l0, h1, l1;
                    split2(v0, h0, l0); split2(v1, h1, l1);
                    bf162 th; th.x = h0; th.y = h1;
                    bf162 tl; tl.x = l0; tl.y = l1;
                    *(bf162*)(S.Chi + o) = th;
                    *(bf162*)(S.Clo + o) = tl;
                }
            }
        }
    }
}

// ---------------------------------------------------------------------------
// weight prepack: W(nc,k) fp32 -> Baug(nc,2k) bf16 rows [hi | lo]
// ---------------------------------------------------------------------------
struct PPk { const float* w; bf16* o; int nc; int k; };
struct PPargs { PPk e[15]; };
__global__ void k_prepack(PPargs pa) {
    PPk p = pa.e[blockIdx.y];
    int tot = p.nc * p.k;
    for (int i = blockIdx.x * 256 + threadIdx.x; i < tot; i += gridDim.x * 256) {
        float x = p.w[i];
        bf16 h, l; split2(x, h, l);
        int r = i / p.k, kk = i - r * p.k;
        bf16* row = p.o + (size_t)r * 2 * p.k;
        row[kk] = h; row[p.k + kk] = l;
    }
}

// ---------------------------------------------------------------------------
// elementwise stages
// ---------------------------------------------------------------------------
// vec (N,64,3) fp32 -> split planes [d][node][c]
__global__ void k_prep(const float* __restrict__ h_vec, bf16* __restrict__ vhi, int Nn) {
    size_t PV = (size_t)3 * Nn * 64;
    bf16* vlo = vhi + PV;
    int i = blockIdx.x * 256 + threadIdx.x;
    if (i >= Nn * 64) return;
    int node = i >> 6, c = i & 63;
#pragma unroll
    for (int d = 0; d < 3; d++) {
        float x = h_vec[(size_t)node * 192 + c * 3 + d];
        bf16 h, l; split2(x, h, l);
        size_t o = (size_t)d * Nn * 64 + (size_t)node * 64 + c;
        vhi[o] = h; vlo[o] = l;
    }
}

// X = [ |vi| , h_sca + te[t] ]  (split).  y: 0=att, 1=net
__global__ void k_buildX(const bf16* __restrict__ viA, const bf16* __restrict__ viN,
                         const float* __restrict__ h_sca, const float* __restrict__ te,
                         const int* __restrict__ tptr,
                         bf16* __restrict__ XaH, bf16* __restrict__ XnH, int Nn) {
    const bf16* vi = blockIdx.y ? viN : viA;
    bf16* Xh = blockIdx.y ? XnH : XaH;
    bf16* Xl = Xh + (size_t)Nn * 320;
    size_t P = (size_t)Nn * 64, PV = 3 * P;
    int i = blockIdx.x * 256 + threadIdx.x;
    int half = Nn * 64;
    if (i < half) {
        int node = i >> 6, c = i & 63;
        size_t q = (size_t)node * 64 + c;
        float a = join2(vi[q], vi[PV + q]);
        float b = join2(vi[q + P], vi[PV + q + P]);
        float d = join2(vi[q + 2 * P], vi[PV + q + 2 * P]);
        float x = sqrtf(a * a + b * b + d * d);
        bf16 h, l; split2(x, h, l);
        size_t o = (size_t)node * 320 + c;
        Xh[o] = h; Xl[o] = l;
    } else if (i < 2 * half) {
        int j = i - half;
        int node = j >> 6, q4 = (j & 63) * 4;
        int t = *tptr;
        float4 hs = *(const float4*)(h_sca + (size_t)node * 256 + q4);
        float4 tv = *(const float4*)(te + (size_t)t * 256 + q4);
        float x[4] = {hs.x + tv.x, hs.y + tv.y, hs.z + tv.z, hs.w + tv.w};
        size_t o = (size_t)node * 320 + 64 + q4;
        bf16 h0, l0, h1, l1;
        split2(x[0], h0, l0); split2(x[1], h1, l1);
        bf162 th; th.x = h0; th.y = h1; bf162 tl; tl.x = l0; tl.y = l1;
        *(bf162*)(Xh + o) = th; *(bf162*)(Xl + o) = tl;
        split2(x[2], h0, l0); split2(x[3], h1, l1);
        th.x = h0; th.y = h1; tl.x = l0; tl.y = l1;
        *(bf162*)(Xh + o + 2) = th; *(bf162*)(Xl + o + 2) = tl;
    }
}

// vn_lrelu on split (u, d) -> split v.  y: 0=att, 1=net
__global__ void k_vnlrelu(const bf16* __restrict__ ua, const bf16* __restrict__ da,
                          const bf16* __restrict__ un, const bf16* __restrict__ dn,
                          bf16* __restrict__ vaS, bf16* __restrict__ vnS, int Nn) {
    const bf16* u  = blockIdx.y ? un : ua;
    const bf16* dd = blockIdx.y ? dn : da;
    bf16* vh = blockIdx.y ? vnS : vaS;
    size_t P = (size_t)Nn * 64, PV = 3 * P;
    bf16* vl = vh + PV;
    int i = blockIdx.x * 256 + threadIdx.x;
    if (i >= Nn * 64) return;
    float u0 = join2(u[i], u[PV + i]);
    float u1 = join2(u[i + P], u[PV + i + P]);
    float u2 = join2(u[i + 2 * P], u[PV + i + 2 * P]);
    float d0 = join2(dd[i], dd[PV + i]);
    float d1 = join2(dd[i + P], dd[PV + i + P]);
    float d2 = join2(dd[i + 2 * P], dd[PV + i + 2 * P]);
    float dot = u0 * d0 + u1 * d1 + u2 * d2;
    float dsq = d0 * d0 + d1 * d1 + d2 * d2;
    float s = dot / (dsq + EPSF);
    float r0, r1, r2;
    if (dot >= 0.f) { r0 = u0; r1 = u1; r2 = u2; }
    else {
        r0 = SLOPEF * u0 + (1.f - SLOPEF) * (u0 - s * d0);
        r1 = SLOPEF * u1 + (1.f - SLOPEF) * (u1 - s * d1);
        r2 = SLOPEF * u2 + (1.f - SLOPEF) * (u2 - s * d2);
    }
    bf16 h, l;
    split2(r0, h, l); vh[i] = h;           vl[i] = l;
    split2(r1, h, l); vh[i + P] = h;       vl[i + P] = l;
    split2(r2, h, l); vh[i + 2 * P] = h;   vl[i + 2 * P] = l;
}

// X2 = [ |vi2n| , lrelu(Sn) ]  (split in, split out)
__global__ void k_buildX2(const bf16* __restrict__ vi2, const bf16* __restrict__ Sn,
                          bf16* __restrict__ Xh, int Nn) {
    bf16* Xl = Xh + (size_t)Nn * 320;
    size_t P = (size_t)Nn * 64, PV = 3 * P;
    const bf16* Snl = Sn + (size_t)Nn * 256;
    int i = blockIdx.x * 256 + threadIdx.x;
    int half = Nn * 64;
    if (i < half) {
        int node = i >> 6, c = i & 63;
        size_t q = (size_t)node * 64 + c;
        float a = join2(vi2[q], vi2[PV + q]);
        float b = join2(vi2[q + P], vi2[PV + q + P]);
        float d = join2(vi2[q + 2 * P], vi2[PV + q + 2 * P]);
        float x = sqrtf(a * a + b * b + d * d);
        bf16 h, l; split2(x, h, l);
        size_t o = (size_t)node * 320 + c;
        Xh[o] = h; Xl[o] = l;
    } else if (i < 2 * half) {
        int j = i - half;
        int node = j >> 6, q4 = (j & 63) * 4;
        size_t so = (size_t)node * 256 + q4;
        bf162 sh0 = *(const bf162*)(Sn + so), sh1 = *(const bf162*)(Sn + so + 2);
        bf162 sl0 = *(const bf162*)(Snl + so), sl1 = *(const bf162*)(Snl + so + 2);
        float x[4] = {join2(sh0.x, sl0.x), join2(sh0.y, sl0.y),
                      join2(sh1.x, sl1.x), join2(sh1.y, sl1.y)};
#pragma unroll
        for (int e = 0; e < 4; e++) x[e] = (x[e] >= 0.f) ? x[e] : SLOPEF * x[e];
        size_t o = (size_t)node * 320 + 64 + q4;
        bf16 h0, l0, h1, l1;
        split2(x[0], h0, l0); split2(x[1], h1, l1);
        bf162 th; th.x = h0; th.y = h1; bf162 tl; tl.x = l0; tl.y = l1;
        *(bf162*)(Xh + o) = th; *(bf162*)(Xl + o) = tl;
        split2(x[2], h0, l0); split2(x[3], h1, l1);
        th.x = h0; th.y = h1; tl.x = l0; tl.y = l1;
        *(bf162*)(Xh + o + 2) = th; *(bf162*)(Xl + o + 2) = tl;
    }
}

// att[n] = Ws[0:64].|vi2a| + Ws[64:320].lrelu(Sa)   (split inputs)
__global__ void k_att(const bf16* __restrict__ vi2a, const bf16* __restrict__ Sa,
                      const float* __restrict__ Ws, float* __restrict__ att, int Nn) {
    __shared__ float ws[320];
    int tid = threadIdx.x, w = tid >> 5, lane = tid & 31;
    for (int i = tid; i < 320; i += 256) ws[i] = Ws[i];
    __syncthreads();
    int node = blockIdx.x * 8 + w;
    if (node >= Nn) return;
    size_t P = (size_t)Nn * 64, PV = 3 * P;
    const bf16* Sal = Sa + (size_t)Nn * 256;
    float p = 0.f;
    for (int c = lane; c < 64; c += 32) {
        size_t q = (size_t)node * 64 + c;
        float a = join2(vi2a[q], vi2a[PV + q]);
        float b = join2(vi2a[q + P], vi2a[PV + q + P]);
        float d = join2(vi2a[q + 2 * P], vi2a[PV + q + 2 * P]);
        p = fmaf(ws[c], sqrtf(a * a + b * b + d * d), p);
    }
    for (int k = lane; k < 256; k += 32) {
        size_t q = (size_t)node * 256 + k;
        float sv = join2(Sa[q], Sal[q]);
        sv = (sv >= 0.f) ? sv : SLOPEF * sv;
        p = fmaf(ws[64 + k], sv, p);
    }
#pragma unroll
    for (int o = 16; o > 0; o >>= 1) p += __shfl_down_sync(0xffffffff, p, o);
    if (lane == 0) att[node] = p;
}

__global__ void k_segstart(const int* __restrict__ bid, int n, int B, int* __restrict__ start) {
    int b = blockIdx.x * blockDim.x + threadIdx.x;
    if (b > B) return;
    int lo = 0, hi = n;
    while (lo < hi) { int mid = (lo + hi) >> 1; if (bid[mid] < b) lo = mid + 1; else hi = mid; }
    start[b] = lo;
}

__global__ void k_softmax(const float* __restrict__ att, const int* __restrict__ start,
                          float* __restrict__ w) {
    int b = blockIdx.x;
    int s = start[b], e = start[b + 1];
    if (s >= e) return;
    __shared__ float red[256];
    int tid = threadIdx.x;
    float m = -INFINITY;
    for (int i = s + tid; i < e; i += 256) m = fmaxf(m, att[i]);
    red[tid] = m; __syncthreads();
    for (int o = 128; o > 0; o >>= 1) { if (tid < o) red[tid] = fmaxf(red[tid], red[tid + o]); __syncthreads(); }
    m = red[0]; __syncthreads();
    float zs = 0.f;
    for (int i = s + tid; i < e; i += 256) zs += __expf(att[i] - m);
    red[tid] = zs; __syncthreads();
    for (int o = 128; o > 0; o >>= 1) { if (tid < o) red[tid] += red[tid + o]; __syncthreads(); }
    float inv = 1.f / red[0];
    for (int i = s + tid; i < e; i += 256) w[i] = __expf(att[i] - m) * inv;
}

// fs split rows [n,256]; fv split planes [d][node][64]
__global__ void k_reduce(const float* __restrict__ w, const bf16* __restrict__ fs,
                         const bf16* __restrict__ fv, const float* __restrict__ pos,
                         const int* __restrict__ start, int B, int Nn, float* __restrict__ out) {
    int b = blockIdx.x, j = threadIdx.x;
    int s = start[b], e = start[b + 1];
    size_t P = (size_t)Nn * 64, PV = 3 * P;
    const bf16* fsl = fs + (size_t)Nn * 256;
    int c = j / 3, d = j - c * 3;
    float a256 = 0.f, a192 = 0.f, a3 = 0.f;
    for (int i = s; i < e; i++) {
        float wi = w[i];
        size_t q = (size_t)i * 256 + j;
        a256 = fmaf(wi, join2(fs[q], fsl[q]), a256);
        if (j < 192) {
            size_t qv = (size_t)d * P + (size_t)i * 64 + c;
            a192 = fmaf(wi, join2(fv[qv], fv[PV + qv]), a192);
        }
        if (j < 3) a3 = fmaf(wi, pos[(size_t)i * 3 + j], a3);
    }
    out[(size_t)b * 256 + j] = a256;
    if (j < 192) out[(size_t)B * 256 + (size_t)b * 192 + j] = a192;
    if (j < 3)   out[(size_t)B * 256 + (size_t)B * 192 + (size_t)b * 3 + j] = a3;
}

// ---------------------------------------------------------------------------
extern "C" void kernel_launch(void* const* d_in, const int* in_sizes, int n_in,
                              void* d_out, int out_size) {
    const float* h_sca = (const float*)d_in[0];
    const float* h_vec = (const float*)d_in[1];
    const float* pos   = (const float*)d_in[2];
    const float* te    = (const float*)d_in[3];
    const float* W[26];
    for (int i = 4; i <= 25; i++) W[i] = (const float*)d_in[i];
    const int* tptr = (const int*)d_in[26];
    const int* bid  = (const int*)d_in[27];

    int n = in_sizes[0] / 256;
    int B = out_size / 451;

    bf16 *vecS, *viAs, *viNs, *uas, *uns, *das, *dns, *vas, *vns, *Xa, *Xn, *Sas, *Sns, *Baug;
    float *Ga, *Gn, *att, *wgt;
    int* segs;
    cudaGetSymbolAddress((void**)&vecS, g_vecS);
    cudaGetSymbolAddress((void**)&viAs, g_viAs);
    cudaGetSymbolAddress((void**)&viNs, g_viNs);
    cudaGetSymbolAddress((void**)&uas,  g_uas);
    cudaGetSymbolAddress((void**)&uns,  g_uns);
    cudaGetSymbolAddress((void**)&das,  g_das);
    cudaGetSymbolAddress((void**)&dns,  g_dns);
    cudaGetSymbolAddress((void**)&vas,  g_vas);
    cudaGetSymbolAddress((void**)&vns,  g_vns);
    cudaGetSymbolAddress((void**)&Xa,   g_Xa);
    cudaGetSymbolAddress((void**)&Xn,   g_Xn);
    cudaGetSymbolAddress((void**)&Sas,  g_Sas);
    cudaGetSymbolAddress((void**)&Sns,  g_Sns);
    cudaGetSymbolAddress((void**)&Baug, g_Baug);
    cudaGetSymbolAddress((void**)&Ga,   g_Ga);
    cudaGetSymbolAddress((void**)&Gn,   g_Gn);
    cudaGetSymbolAddress((void**)&att,  g_att);
    cudaGetSymbolAddress((void**)&wgt,  g_w);
    cudaGetSymbolAddress((void**)&segs, g_seg);

    // prepack weights -> Baug rows [hi|lo] (2K)
    static const int widx[15] = {4,15, 6,17, 7,18, 5,16, 9,20, 10,21, 23,24,22};
    static const int wnc[15]  = {64,64, 256,256, 64,64, 64,64, 64,64, 64,64, 256,64,64};
    static const int wk[15]   = {64,64, 320,320, 256,256, 64,64, 64,64, 64,64, 320,256,64};
    PPargs pa;
    size_t boff[15]; size_t acc = 0;
    for (int i = 0; i < 15; i++) {
        boff[i] = acc;
        pa.e[i] = PPk{W[widx[i]], Baug + acc, wnc[i], wk[i]};
        acc += (size_t)wnc[i] * 2 * wk[i];
    }
    const bf16 *B_a1Wv1 = Baug + boff[0],  *B_n1Wv1 = Baug + boff[1];
    const bf16 *B_a1Ws  = Baug + boff[2],  *B_n1Ws  = Baug + boff[3];
    const bf16 *B_a1Wg  = Baug + boff[4],  *B_n1Wg  = Baug + boff[5];
    const bf16 *B_a1Wv2 = Baug + boff[6],  *B_n1Wv2 = Baug + boff[7];
    const bf16 *B_a1Wd  = Baug + boff[8],  *B_n1Wd  = Baug + boff[9];
    const bf16 *B_a2Wv1 = Baug + boff[10], *B_n2Wv1 = Baug + boff[11];
    const bf16 *B_n2Ws  = Baug + boff[12], *B_n2Wg  = Baug + boff[13];
    const bf16 *B_n2Wv2 = Baug + boff[14];

    size_t PV = (size_t)3 * n * 64;
    int M3 = 3 * n;
    int g128_3 = (M3 + 127) / 128;
    int g128_1 = (n + 127) / 128;

    constexpr int SM64  = (2 * 128 * 40 + 4 * 64 * 40) * 2;    // 40960 B
    constexpr int SM256 = (2 * 128 * 40 + 4 * 256 * 40) * 2;   // 102400 B
    cudaFuncSetAttribute((const void*)gemm_bf16<64>,
                         cudaFuncAttributeMaxDynamicSharedMemorySize, SM64);
    cudaFuncSetAttribute((const void*)gemm_bf16<256>,
                         cudaFuncAttributeMaxDynamicSharedMemorySize, SM256);

    auto GS = [](const bf16* ah, const bf16* al, const bf16* b, float* cf,
                 bf16* ch, bf16* cl, const float* bias, const float* gate, int act) {
        GSet g; g.Ahi = ah; g.Alo = al; g.B = b; g.Cf = cf; g.Chi = ch; g.Clo = cl;
        g.bias = bias; g.gate = gate; g.act = act; return g;
    };

    k_prepack<<<dim3(64, 15), 256>>>(pa);
    k_prep<<<(n * 64 + 255) / 256, 256>>>(h_vec, vecS, n);

    // vi = Wv1 @ vec (pair) -> split
    gemm_bf16<64><<<dim3(g128_3, 2), 256, SM64>>>(
        GS(vecS, vecS + PV, B_a1Wv1, nullptr, viAs, viAs + PV, nullptr, nullptr, 0),
        GS(vecS, vecS + PV, B_n1Wv1, nullptr, viNs, viNs + PV, nullptr, nullptr, 0),
        M3, 64, n);
    k_buildX<<<dim3((n * 128 + 255) / 256, 2), 256>>>(viAs, viNs, h_sca, te, tptr, Xa, Xn, n);

    // S = X @ Ws (pair) -> split
    gemm_bf16<256><<<dim3(g128_1, 2), 512, SM256>>>(
        GS(Xa, Xa + (size_t)n * 320, B_a1Ws, nullptr, Sas, Sas + (size_t)n * 256, nullptr, nullptr, 0),
        GS(Xn, Xn + (size_t)n * 320, B_n1Ws, nullptr, Sns, Sns + (size_t)n * 256, nullptr, nullptr, 0),
        n, 320, n);
    // gates (pair) -> fp32
    gemm_bf16<64><<<dim3(g128_1, 2), 256, SM64>>>(
        GS(Sas, Sas + (size_t)n * 256, B_a1Wg, Ga, nullptr, nullptr, W[8], nullptr, 1),
        GS(Sns, Sns + (size_t)n * 256, B_n1Wg, Gn, nullptr, nullptr, W[19], nullptr, 1),
        n, 256, n);
    // u = gate * (Wv2 @ vi) (pair) -> split
    gemm_bf16<64><<<dim3(g128_3, 2), 256, SM64>>>(
        GS(viAs, viAs + PV, B_a1Wv2, nullptr, uas, uas + PV, nullptr, Ga, 0),
        GS(viNs, viNs + PV, B_n1Wv2, nullptr, uns, uns + PV, nullptr, Gn, 0),
        M3, 64, n);
    // d = Wd @ u (pair) -> split
    gemm_bf16<64><<<dim3(g128_3, 2), 256, SM64>>>(
        GS(uas, uas + PV, B_a1Wd, nullptr, das, das + PV, nullptr, nullptr, 0),
        GS(uns, uns + PV, B_n1Wd, nullptr, dns, dns + PV, nullptr, nullptr, 0),
        M3, 64, n);
    k_vnlrelu<<<dim3((n * 64 + 255) / 256, 2), 256>>>(uas, das, uns, dns, vas, vns, n);

    // vi2 = Wv1' @ v (pair): att -> uas (reuse), net -> viAs (reuse)
    gemm_bf16<64><<<dim3(g128_3, 2), 256, SM64>>>(
        GS(vas, vas + PV, B_a2Wv1, nullptr, uas, uas + PV, nullptr, nullptr, 0),
        GS(vns, vns + PV, B_n2Wv1, nullptr, viAs, viAs + PV, nullptr, nullptr, 0),
        M3, 64, n);
    k_att<<<(n + 7) / 8, 256>>>(uas, Sas, W[12], att, n);
    k_buildX2<<<(n * 128 + 255) / 256, 256>>>(viAs, Sns, Xa, n);

    // fs = X2 @ n2Ws -> Sas (reuse, split)
    {
        GSet g = GS(Xa, Xa + (size_t)n * 320, B_n2Ws, nullptr, Sas, Sas + (size_t)n * 256, nullptr, nullptr, 0);
        gemm_bf16<256><<<dim3(g128_1, 1), 512, SM256>>>(g, g, n, 320, n);
    }
    // gate2 -> Ga (reuse)
    {
        GSet g = GS(Sas, Sas + (size_t)n * 256, B_n2Wg, Ga, nullptr, nullptr, W[25], nullptr, 1);
        gemm_bf16<64><<<dim3(g128_1, 1), 256, SM64>>>(g, g, n, 256, n);
    }
    // fv = gate2 * (n2Wv2 @ vi2n) -> vas (reuse, split)
    {
        GSet g = GS(viAs, viAs + PV, B_n2Wv2, nullptr, vas, vas + PV, nullptr, Ga, 0);
        gemm_bf16<64><<<dim3(g128_3, 1), 256, SM64>>>(g, g, M3, 64, n);
    }

    k_segstart<<<(B + 1 + 255) / 256, 256>>>(bid, n, B, segs);
    k_softmax<<<B, 256>>>(att, segs, wgt);
    k_reduce<<<B, 256>>>(wgt, Sas, vas, pos, segs, B, n, (float*)d_out);
}

// round 8
// speedup vs baseline: 2.5644x; 1.0262x over previous
#include <cuda_runtime.h>
#include <cuda_bf16.h>
#include <math.h>
#include <stdint.h>

typedef __nv_bfloat16 bf16;
typedef __nv_bfloat162 bf162;

#define MAXN   120000
#define SLOPEF 0.01f
#define EPSF   1e-6f
#define PVMAX  (3*MAXN*64)

// ---------------- static device scratch (bf16 split: [hi | lo]) -------------
__device__ __align__(16) bf16  g_vecS[2*PVMAX];
__device__ __align__(16) bf16  g_viAs[2*PVMAX];
__device__ __align__(16) bf16  g_viNs[2*PVMAX];   // later: vi2n
__device__ __align__(16) bf16  g_uas [2*PVMAX];
__device__ __align__(16) bf16  g_uns [2*PVMAX];
__device__ __align__(16) bf16  g_vas [2*PVMAX];   // later: fv
__device__ __align__(16) bf16  g_vns [2*PVMAX];
__device__ __align__(16) bf16  g_scaX[2*MAXN*256];
__device__ __align__(16) bf16  g_lrS [2*MAXN*256];
__device__ __align__(16) bf16  g_Sas [2*MAXN*256]; // later: fs
__device__ __align__(16) bf16  g_Sns [2*MAXN*256];
__device__ __align__(16) bf16  g_nA1 [2*MAXN*64];
__device__ __align__(16) bf16  g_nN1 [2*MAXN*64];
__device__ __align__(16) bf16  g_nA2 [2*MAXN*64];
__device__ __align__(16) bf16  g_nN2 [2*MAXN*64];
__device__ __align__(16) bf16  g_Baug[1048576];
__device__ float g_Ga  [MAXN*64];
__device__ float g_Gn  [MAXN*64];
__device__ float g_att [MAXN];
__device__ float g_w   [MAXN];
__device__ int   g_seg [4100];

// ---------------- helpers ----------------
__device__ __forceinline__ uint32_t smem_u32(const void* p) {
    return (uint32_t)__cvta_generic_to_shared(p);
}
__device__ __forceinline__ void split2(float x, bf16& h, bf16& l) {
    h = __float2bfloat16(x);
    l = __float2bfloat16(x - __bfloat162float(h));
}
__device__ __forceinline__ float join2(bf16 h, bf16 l) {
    return __bfloat162float(h) + __bfloat162float(l);
}
__device__ __forceinline__ void store_split2(bf16* H, bf16* L, size_t o, float v0, float v1) {
    bf16 h0, l0, h1, l1;
    split2(v0, h0, l0); split2(v1, h1, l1);
    bf162 th; th.x = h0; th.y = h1;
    bf162 tl; tl.x = l0; tl.y = l1;
    *(bf162*)(H + o) = th;
    *(bf162*)(L + o) = tl;
}

#define MMA16816(d, a, b)                                                     \
    asm volatile("mma.sync.aligned.m16n8k16.row.col.f32.bf16.bf16.f32 "      \
        "{%0,%1,%2,%3}, {%4,%5,%6,%7}, {%8,%9}, {%0,%1,%2,%3};"              \
        : "+f"((d)[0]), "+f"((d)[1]), "+f"((d)[2]), "+f"((d)[3])             \
        : "r"((a)[0]), "r"((a)[1]), "r"((a)[2]), "r"((a)[3]),                \
          "r"((b)[0]), "r"((b)[1]))

#define LDSM_X4(r0, r1, r2, r3, addr)                                        \
    asm volatile("ldmatrix.sync.aligned.m8n8.x4.shared.b16 {%0,%1,%2,%3}, [%4];" \
        : "=r"(r0), "=r"(r1), "=r"(r2), "=r"(r3) : "r"(addr))

#define CP_ASYNC16(sa, ga)                                                   \
    asm volatile("cp.async.cg.shared.global [%0], [%1], 16;" :: "r"(sa), "l"(ga))
#define CP_ASYNC16_P(sa, ga, p)                                              \
    asm volatile("cp.async.cg.shared.global [%0], [%1], 16, %2;" :: "r"(sa), "l"(ga), "r"(p))
#define CP_COMMIT() asm volatile("cp.async.commit_group;")
#define CP_WAIT1()  asm volatile("cp.async.wait_group 1;")
#define CP_WAIT0()  asm volatile("cp.async.wait_group 0;")

// ---------------------------------------------------------------------------
// generic HMMA GEMM with two A regions: cols [0,K1) from A1, [K1,K) from A2
// C[M,NC] = epi( (A1|A2)hi+lo @ B^T ), B prepacked [NC][hi K | lo K]
// NC=64: 256 thr (8 warps 4x2). NC=256: 512 thr (16 warps 4x4).
// ---------------------------------------------------------------------------
struct GSet {
    const bf16 *A1h, *A1l, *A2h, *A2l;
    int K1;
    const bf16* B;
    float* Cf; bf16 *Chi, *Clo;
    bf16 *Lhi, *Llo;                 // optional lrelu split side-output
    const float *bias, *gate;
    int act;
};

template <int NC>
__global__ void __launch_bounds__(NC == 256 ? 512 : 256)
gemm_bf16(GSet s0, GSet s1, int M, int K, int Nn) {
    constexpr int NTH   = (NC == 256) ? 512 : 256;
    constexpr int NWN   = (NC == 256) ? 4 : 2;
    constexpr int WCOLS = NC / NWN;
    constexpr int NT    = WCOLS / 8;
    constexpr int A_ST  = 128 * 40;
    constexpr int B_ST  = NC * 40;

    extern __shared__ bf16 sm[];
    bf16* smA = sm;
    bf16* smB = sm + 2 * A_ST;

    const int tid = threadIdx.x;
    const int lane = tid & 31, wid = tid >> 5;
    const int wm = wid / NWN, wn = wid % NWN;
    const GSet S = (blockIdx.y == 0) ? s0 : s1;
    const int m0 = blockIdx.x * 128;
    const int KC = K >> 5;
    const int ST = 2 * KC;
    const size_t K2 = (size_t)2 * K;
    const int K2w = K - S.K1;

    float acc[2][NT][4];
#pragma unroll
    for (int i = 0; i < 2; i++)
#pragma unroll
        for (int j = 0; j < NT; j++)
#pragma unroll
            for (int k = 0; k < 4; k++) acc[i][j][k] = 0.f;

    auto load_stage = [&](int s, int buf) {
        bool hp = (s < KC);
        int kc = hp ? s : s - KC;
        int kof = kc * 32;
        const bf16* base; int stride, col;
        if (kof < S.K1) { base = hp ? S.A1h : S.A1l; stride = S.K1; col = kof; }
        else            { base = hp ? S.A2h : S.A2l; stride = K2w;  col = kof - S.K1; }
        for (int i = tid; i < 512; i += NTH) {
            int r = i >> 2, sg = i & 3;
            int m = m0 + r;
            uint32_t sa = smem_u32(smA + buf * A_ST + r * 40 + sg * 8);
            const bf16* ga = base + ((m < M) ? ((size_t)m * stride + col + sg * 8) : 0);
            CP_ASYNC16_P(sa, ga, (m < M) ? 16 : 0);
        }
        int c0 = kc * 32;
        for (int i = tid; i < NC * 4; i += NTH) {
            int r = i >> 2, sg = i & 3;
            uint32_t sa = smem_u32(smB + (buf * 2 + 0) * B_ST + r * 40 + sg * 8);
            CP_ASYNC16(sa, S.B + (size_t)r * K2 + c0 + sg * 8);
        }
        if (hp) {
            int c1 = K + kc * 32;
            for (int i = tid; i < NC * 4; i += NTH) {
                int r = i >> 2, sg = i & 3;
                uint32_t sa = smem_u32(smB + (buf * 2 + 1) * B_ST + r * 40 + sg * 8);
                CP_ASYNC16(sa, S.B + (size_t)r * K2 + c1 + sg * 8);
            }
        }
        CP_COMMIT();
    };

    load_stage(0, 0);
    for (int s = 0; s < ST; s++) {
        int buf = s & 1;
        if (s + 1 < ST) { load_stage(s + 1, buf ^ 1); CP_WAIT1(); }
        else            { CP_WAIT0(); }
        __syncthreads();
        const bool dual = (s < KC);
#pragma unroll
        for (int kk = 0; kk < 2; kk++) {
            const int k16 = kk * 16;
            uint32_t a[2][4];
#pragma unroll
            for (int mt = 0; mt < 2; mt++) {
                uint32_t ad = smem_u32(smA + buf * A_ST
                                       + (wm * 32 + mt * 16 + (lane & 15)) * 40
                                       + k16 + (lane >> 4) * 8);
                LDSM_X4(a[mt][0], a[mt][1], a[mt][2], a[mt][3], ad);
            }
#pragma unroll
            for (int sub = 0; sub < 2; sub++) {
                if (sub == 1 && !dual) break;
                uint32_t b[NT][2];
#pragma unroll
                for (int half = 0; half < NT / 2; half++) {
                    int g = lane >> 3, r = lane & 7;
                    int nt8 = (g >> 1), ko = (g & 1) * 8;
                    uint32_t ad = smem_u32(smB + (buf * 2 + sub) * B_ST
                                           + (wn * WCOLS + half * 16 + nt8 * 8 + r) * 40
                                           + k16 + ko);
                    uint32_t r0, r1, r2, r3;
                    LDSM_X4(r0, r1, r2, r3, ad);
                    b[half * 2 + 0][0] = r0; b[half * 2 + 0][1] = r1;
                    b[half * 2 + 1][0] = r2; b[half * 2 + 1][1] = r3;
                }
#pragma unroll
                for (int mt = 0; mt < 2; mt++)
#pragma unroll
                    for (int nt = 0; nt < NT; nt++)
                        MMA16816(acc[mt][nt], a[mt], b[nt]);
            }
        }
        __syncthreads();
    }

#pragma unroll
    for (int mt = 0; mt < 2; mt++) {
#pragma unroll
        for (int hh = 0; hh < 2; hh++) {
            int m = m0 + wm * 32 + mt * 16 + (lane >> 2) + hh * 8;
            if (m >= M) continue;
            int node = m % Nn;
#pragma unroll
            for (int nt = 0; nt < NT; nt++) {
                int col = wn * WCOLS + nt * 8 + (lane & 3) * 2;
                float v0 = acc[mt][nt][hh * 2 + 0];
                float v1 = acc[mt][nt][hh * 2 + 1];
                if (S.act) {
                    v0 = 1.f / (1.f + __expf(-(v0 + S.bias[col])));
                    v1 = 1.f / (1.f + __expf(-(v1 + S.bias[col + 1])));
                }
                if (S.gate) {
                    v0 *= S.gate[(size_t)node * 64 + col];
                    v1 *= S.gate[(size_t)node * 64 + col + 1];
                }
                size_t o = (size_t)m * NC + col;
                if (S.Cf) *(float2*)(S.Cf + o) = make_float2(v0, v1);
                if (S.Chi) store_split2(S.Chi, S.Clo, o, v0, v1);
                if (S.Lhi) {
                    float l0 = (v0 >= 0.f) ? v0 : SLOPEF * v0;
                    float l1 = (v1 >= 0.f) ? v1 : SLOPEF * v1;
                    store_split2(S.Lhi, S.Llo, o, l0, l1);
                }
            }
        }
    }
}

// ---------------------------------------------------------------------------
// 3-plane VN GEMM (K=64, NC=64): one block = 128 nodes x 64 cols, loops d=0..2
// internally with B resident in smem. Epilogue holds all 3 components:
//   - optional vn_lrelu against u (Uhi/Ulo planes)
//   - optional plane outputs Chi/Clo, optional norm outputs Nhi/Nlo [n,64]
// ---------------------------------------------------------------------------
struct VSet {
    const bf16 *Ahi, *Alo;      // planes [d][n][64]
    const bf16 *B;              // [64][128]  (hi 64 | lo 64)
    const bf16 *Uhi, *Ulo;      // vn_lrelu input planes (or null)
    bf16 *Chi, *Clo;            // plane outputs (or null)
    bf16 *Nhi, *Nlo;            // norm outputs [n,64] (or null)
};

__global__ void __launch_bounds__(256)
gemm_vn3(VSet s0, VSet s1, int Nn) {
    __shared__ bf16 Bs[64 * 136];
    __shared__ bf16 As[2][128 * 40];
    const int tid = threadIdx.x, lane = tid & 31, wid = tid >> 5;
    const int wm = wid >> 1, wn = wid & 1;
    const VSet S = blockIdx.y ? s1 : s0;
    const int m0 = blockIdx.x * 128;
    const size_t P = (size_t)Nn * 64;

    // B resident: 64 rows x 128 bf16 cols = 16 chunks of 16B per row
    for (int i = tid; i < 1024; i += 256) {
        int r = i >> 4, c8 = i & 15;
        CP_ASYNC16(smem_u32(Bs + r * 136 + c8 * 8), S.B + r * 128 + c8 * 8);
    }
    CP_COMMIT();

    float acc[3][2][4][4];
#pragma unroll
    for (int d = 0; d < 3; d++)
#pragma unroll
        for (int i = 0; i < 2; i++)
#pragma unroll
            for (int j = 0; j < 4; j++)
#pragma unroll
                for (int k = 0; k < 4; k++) acc[d][i][j][k] = 0.f;

    auto loadA = [&](int gs, int buf) {
        int d = gs >> 2, s = gs & 3;
        const bf16* Ab = (s < 2) ? S.Ahi : S.Alo;
        int kof = (s & 1) * 32;
        for (int i = tid; i < 512; i += 256) {
            int r = i >> 2, sg = i & 3;
            int m = m0 + r;
            uint32_t sa = smem_u32(As[buf] + r * 40 + sg * 8);
            const bf16* ga = Ab + d * P + ((m < Nn) ? ((size_t)m * 64 + kof + sg * 8) : 0);
            CP_ASYNC16_P(sa, ga, (m < Nn) ? 16 : 0);
        }
        CP_COMMIT();
    };

    loadA(0, 0);
    for (int gs = 0; gs < 12; gs++) {
        int buf = gs & 1;
        if (gs + 1 < 12) { loadA(gs + 1, buf ^ 1); CP_WAIT1(); }
        else             { CP_WAIT0(); }
        __syncthreads();
        int d = gs >> 2, s = gs & 3;
        bool dual = (s < 2);
        int kc = s & 1;
#pragma unroll
        for (int kk = 0; kk < 2; kk++) {
            const int k16 = kk * 16;
            uint32_t a[2][4];
#pragma unroll
            for (int mt = 0; mt < 2; mt++) {
                uint32_t ad = smem_u32(As[buf] + (wm * 32 + mt * 16 + (lane & 15)) * 40
                                       + k16 + (lane >> 4) * 8);
                LDSM_X4(a[mt][0], a[mt][1], a[mt][2], a[mt][3], ad);
            }
#pragma unroll
            for (int sub = 0; sub < 2; sub++) {
                if (sub == 1 && !dual) break;
                int bcol = sub * 64 + kc * 32;
                uint32_t b[4][2];
                {
                    int g = lane >> 3, r = lane & 7;
                    int nt8 = (g >> 1), ko = (g & 1) * 8;
#pragma unroll
                    for (int half = 0; half < 2; half++) {
                        uint32_t ad = smem_u32(Bs + (wn * 32 + half * 16 + nt8 * 8 + r) * 136
                                               + bcol + k16 + ko);
                        uint32_t r0, r1, r2, r3;
                        LDSM_X4(r0, r1, r2, r3, ad);
                        b[half * 2 + 0][0] = r0; b[half * 2 + 0][1] = r1;
                        b[half * 2 + 1][0] = r2; b[half * 2 + 1][1] = r3;
                    }
                }
#pragma unroll
                for (int mt = 0; mt < 2; mt++)
#pragma unroll
                    for (int nt = 0; nt < 4; nt++)
                        MMA16816(acc[d][mt][nt], a[mt], b[nt]);
            }
        }
        __syncthreads();
    }

    // -------- fused epilogue --------
#pragma unroll
    for (int mt = 0; mt < 2; mt++) {
#pragma unroll
        for (int hh = 0; hh < 2; hh++) {
            int m = m0 + wm * 32 + mt * 16 + (lane >> 2) + hh * 8;
            if (m >= Nn) continue;
#pragma unroll
            for (int nt = 0; nt < 4; nt++) {
                int col = wn * 32 + nt * 8 + (lane & 3) * 2;
                float v[3][2];
#pragma unroll
                for (int d = 0; d < 3; d++) {
                    v[d][0] = acc[d][mt][nt][hh * 2 + 0];
                    v[d][1] = acc[d][mt][nt][hh * 2 + 1];
                }
                if (S.Uhi) {
                    float u[3][2];
#pragma unroll
                    for (int d = 0; d < 3; d++) {
                        size_t q = d * P + (size_t)m * 64 + col;
                        bf162 uh = *(const bf162*)(S.Uhi + q);
                        bf162 ul = *(const bf162*)(S.Ulo + q);
                        u[d][0] = join2(uh.x, ul.x);
                        u[d][1] = join2(uh.y, ul.y);
                    }
#pragma unroll
                    for (int e = 0; e < 2; e++) {
                        float dot = u[0][e] * v[0][e] + u[1][e] * v[1][e] + u[2][e] * v[2][e];
                        float dsq = v[0][e] * v[0][e] + v[1][e] * v[1][e] + v[2][e] * v[2][e];
                        float sc = dot / (dsq + EPSF);
#pragma unroll
                        for (int d = 0; d < 3; d++) {
                            float x = u[d][e];
                            float r = (dot >= 0.f) ? x
                                     : (SLOPEF * x + (1.f - SLOPEF) * (x - sc * v[d][e]));
                            v[d][e] = r;
                        }
                    }
                }
                if (S.Chi) {
#pragma unroll
                    for (int d = 0; d < 3; d++)
                        store_split2(S.Chi, S.Clo, d * P + (size_t)m * 64 + col, v[d][0], v[d][1]);
                }
                if (S.Nhi) {
                    float n0 = sqrtf(v[0][0] * v[0][0] + v[1][0] * v[1][0] + v[2][0] * v[2][0]);
                    float n1 = sqrtf(v[0][1] * v[0][1] + v[1][1] * v[1][1] + v[2][1] * v[2][1]);
                    store_split2(S.Nhi, S.Nlo, (size_t)m * 64 + col, n0, n1);
                }
            }
        }
    }
}

// ---------------------------------------------------------------------------
// weight prepack: W(nc,k) fp32 -> Baug(nc,2k) bf16 rows [hi | lo]
// ---------------------------------------------------------------------------
struct PPk { const float* w; bf16* o; int nc; int k; };
struct PPargs { PPk e[15]; };
__global__ void k_prepack(PPargs pa) {
    PPk p = pa.e[blockIdx.y];
    int tot = p.nc * p.k;
    for (int i = blockIdx.x * 256 + threadIdx.x; i < tot; i += gridDim.x * 256) {
        float x = p.w[i];
        bf16 h, l; split2(x, h, l);
        int r = i / p.k, kk = i - r * p.k;
        bf16* row = p.o + (size_t)r * 2 * p.k;
        row[kk] = h; row[p.k + kk] = l;
    }
}

// ---------------------------------------------------------------------------
// prep: vec -> split planes; sca = h_sca + te[t] -> shared split [n,256]
// ---------------------------------------------------------------------------
__global__ void k_prep(const float* __restrict__ h_vec, const float* __restrict__ h_sca,
                       const float* __restrict__ te, const int* __restrict__ tptr,
                       bf16* __restrict__ vhi, bf16* __restrict__ scah, int Nn) {
    size_t PV = (size_t)3 * Nn * 64;
    bf16* vlo = vhi + PV;
    bf16* scal = scah + (size_t)Nn * 256;
    int i = blockIdx.x * 256 + threadIdx.x;
    int half = Nn * 64;
    if (i < half) {
        int node = i >> 6, c = i & 63;
#pragma unroll
        for (int d = 0; d < 3; d++) {
            float x = h_vec[(size_t)node * 192 + c * 3 + d];
            bf16 h, l; split2(x, h, l);
            size_t o = (size_t)d * Nn * 64 + (size_t)node * 64 + c;
            vhi[o] = h; vlo[o] = l;
        }
    } else if (i < 2 * half) {
        int j = i - half;
        int node = j >> 6, q4 = (j & 63) * 4;
        int t = *tptr;
        float4 hs = *(const float4*)(h_sca + (size_t)node * 256 + q4);
        float4 tv = *(const float4*)(te + (size_t)t * 256 + q4);
        size_t o = (size_t)node * 256 + q4;
        store_split2(scah, scal, o,     hs.x + tv.x, hs.y + tv.y);
        store_split2(scah, scal, o + 2, hs.z + tv.z, hs.w + tv.w);
    }
}

// att[n] = Ws[0:64].|vi2a| + Ws[64:320].lrelu(Sa)
__global__ void k_att(const bf16* __restrict__ Nh, const bf16* __restrict__ Sa,
                      const float* __restrict__ Ws, float* __restrict__ att, int Nn) {
    __shared__ float ws[320];
    int tid = threadIdx.x, w = tid >> 5, lane = tid & 31;
    for (int i = tid; i < 320; i += 256) ws[i] = Ws[i];
    __syncthreads();
    int node = blockIdx.x * 8 + w;
    if (node >= Nn) return;
    const bf16* Nl = Nh + (size_t)Nn * 64;
    const bf16* Sal = Sa + (size_t)Nn * 256;
    float p = 0.f;
    for (int c = lane; c < 64; c += 32) {
        size_t q = (size_t)node * 64 + c;
        p = fmaf(ws[c], join2(Nh[q], Nl[q]), p);
    }
    for (int k = lane; k < 256; k += 32) {
        size_t q = (size_t)node * 256 + k;
        float sv = join2(Sa[q], Sal[q]);
        sv = (sv >= 0.f) ? sv : SLOPEF * sv;
        p = fmaf(ws[64 + k], sv, p);
    }
#pragma unroll
    for (int o = 16; o > 0; o >>= 1) p += __shfl_down_sync(0xffffffff, p, o);
    if (lane == 0) att[node] = p;
}

__global__ void k_segstart(const int* __restrict__ bid, int n, int B, int* __restrict__ start) {
    int b = blockIdx.x * blockDim.x + threadIdx.x;
    if (b > B) return;
    int lo = 0, hi = n;
    while (lo < hi) { int mid = (lo + hi) >> 1; if (bid[mid] < b) lo = mid + 1; else hi = mid; }
    start[b] = lo;
}

__global__ void k_softmax(const float* __restrict__ att, const int* __restrict__ start,
                          float* __restrict__ w) {
    int b = blockIdx.x;
    int s = start[b], e = start[b + 1];
    if (s >= e) return;
    __shared__ float red[256];
    int tid = threadIdx.x;
    float m = -INFINITY;
    for (int i = s + tid; i < e; i += 256) m = fmaxf(m, att[i]);
    red[tid] = m; __syncthreads();
    for (int o = 128; o > 0; o >>= 1) { if (tid < o) red[tid] = fmaxf(red[tid], red[tid + o]); __syncthreads(); }
    m = red[0]; __syncthreads();
    float zs = 0.f;
    for (int i = s + tid; i < e; i += 256) zs += __expf(att[i] - m);
    red[tid] = zs; __syncthreads();
    for (int o = 128; o > 0; o >>= 1) { if (tid < o) red[tid] += red[tid + o]; __syncthreads(); }
    float inv = 1.f / red[0];
    for (int i = s + tid; i < e; i += 256) w[i] = __expf(att[i] - m) * inv;
}

__global__ void k_reduce(const float* __restrict__ w, const bf16* __restrict__ fs,
                         const bf16* __restrict__ fv, const float* __restrict__ pos,
                         const int* __restrict__ start, int B, int Nn, float* __restrict__ out) {
    int b = blockIdx.x, j = threadIdx.x;
    int s = start[b], e = start[b + 1];
    size_t P = (size_t)Nn * 64, PV = 3 * P;
    const bf16* fsl = fs + (size_t)Nn * 256;
    int c = j / 3, d = j - c * 3;
    float a256 = 0.f, a192 = 0.f, a3 = 0.f;
    for (int i = s; i < e; i++) {
        float wi = w[i];
        size_t q = (size_t)i * 256 + j;
        a256 = fmaf(wi, join2(fs[q], fsl[q]), a256);
        if (j < 192) {
            size_t qv = (size_t)d * P + (size_t)i * 64 + c;
            a192 = fmaf(wi, join2(fv[qv], fv[PV + qv]), a192);
        }
        if (j < 3) a3 = fmaf(wi, pos[(size_t)i * 3 + j], a3);
    }
    out[(size_t)b * 256 + j] = a256;
    if (j < 192) out[(size_t)B * 256 + (size_t)b * 192 + j] = a192;
    if (j < 3)   out[(size_t)B * 256 + (size_t)B * 192 + (size_t)b * 3 + j] = a3;
}

// ---------------------------------------------------------------------------
extern "C" void kernel_launch(void* const* d_in, const int* in_sizes, int n_in,
                              void* d_out, int out_size) {
    const float* h_sca = (const float*)d_in[0];
    const float* h_vec = (const float*)d_in[1];
    const float* pos   = (const float*)d_in[2];
    const float* te    = (const float*)d_in[3];
    const float* W[26];
    for (int i = 4; i <= 25; i++) W[i] = (const float*)d_in[i];
    const int* tptr = (const int*)d_in[26];
    const int* bid  = (const int*)d_in[27];

    int n = in_sizes[0] / 256;
    int B = out_size / 451;

    bf16 *vecS, *viAs, *viNs, *uas, *uns, *vas, *vns, *scaX, *lrS, *Sas, *Sns;
    bf16 *nA1, *nN1, *nA2, *nN2, *Baug;
    float *Ga, *Gn, *att, *wgt;
    int* segs;
    cudaGetSymbolAddress((void**)&vecS, g_vecS);
    cudaGetSymbolAddress((void**)&viAs, g_viAs);
    cudaGetSymbolAddress((void**)&viNs, g_viNs);
    cudaGetSymbolAddress((void**)&uas,  g_uas);
    cudaGetSymbolAddress((void**)&uns,  g_uns);
    cudaGetSymbolAddress((void**)&vas,  g_vas);
    cudaGetSymbolAddress((void**)&vns,  g_vns);
    cudaGetSymbolAddress((void**)&scaX, g_scaX);
    cudaGetSymbolAddress((void**)&lrS,  g_lrS);
    cudaGetSymbolAddress((void**)&Sas,  g_Sas);
    cudaGetSymbolAddress((void**)&Sns,  g_Sns);
    cudaGetSymbolAddress((void**)&nA1,  g_nA1);
    cudaGetSymbolAddress((void**)&nN1,  g_nN1);
    cudaGetSymbolAddress((void**)&nA2,  g_nA2);
    cudaGetSymbolAddress((void**)&nN2,  g_nN2);
    cudaGetSymbolAddress((void**)&Baug, g_Baug);
    cudaGetSymbolAddress((void**)&Ga,   g_Ga);
    cudaGetSymbolAddress((void**)&Gn,   g_Gn);
    cudaGetSymbolAddress((void**)&att,  g_att);
    cudaGetSymbolAddress((void**)&wgt,  g_w);
    cudaGetSymbolAddress((void**)&segs, g_seg);

    static const int widx[15] = {4,15, 6,17, 7,18, 5,16, 9,20, 10,21, 23,24,22};
    static const int wnc[15]  = {64,64, 256,256, 64,64, 64,64, 64,64, 64,64, 256,64,64};
    static const int wk[15]   = {64,64, 320,320, 256,256, 64,64, 64,64, 64,64, 320,256,64};
    PPargs pa;
    size_t boff[15]; size_t acc = 0;
    for (int i = 0; i < 15; i++) {
        boff[i] = acc;
        pa.e[i] = PPk{W[widx[i]], Baug + acc, wnc[i], wk[i]};
        acc += (size_t)wnc[i] * 2 * wk[i];
    }
    const bf16 *B_a1Wv1 = Baug + boff[0],  *B_n1Wv1 = Baug + boff[1];
    const bf16 *B_a1Ws  = Baug + boff[2],  *B_n1Ws  = Baug + boff[3];
    const bf16 *B_a1Wg  = Baug + boff[4],  *B_n1Wg  = Baug + boff[5];
    const bf16 *B_a1Wv2 = Baug + boff[6],  *B_n1Wv2 = Baug + boff[7];
    const bf16 *B_a1Wd  = Baug + boff[8],  *B_n1Wd  = Baug + boff[9];
    const bf16 *B_a2Wv1 = Baug + boff[10], *B_n2Wv1 = Baug + boff[11];
    const bf16 *B_n2Ws  = Baug + boff[12], *B_n2Wg  = Baug + boff[13];
    const bf16 *B_n2Wv2 = Baug + boff[14];

    size_t PV = (size_t)3 * n * 64;
    size_t H64 = (size_t)n * 64, H256 = (size_t)n * 256;
    int M3 = 3 * n;
    int gv = (n + 127) / 128;
    int g3 = (M3 + 127) / 128;

    constexpr int SM64  = (2 * 128 * 40 + 4 * 64 * 40) * 2;
    constexpr int SM256 = (2 * 128 * 40 + 4 * 256 * 40) * 2;
    cudaFuncSetAttribute((const void*)gemm_bf16<64>,
                         cudaFuncAttributeMaxDynamicSharedMemorySize, SM64);
    cudaFuncSetAttribute((const void*)gemm_bf16<256>,
                         cudaFuncAttributeMaxDynamicSharedMemorySize, SM256);

    auto GS = [](const bf16* a1h, const bf16* a1l, const bf16* a2h, const bf16* a2l, int K1,
                 const bf16* b, float* cf, bf16* ch, bf16* cl, bf16* lh, bf16* ll,
                 const float* bias, const float* gate, int act) {
        GSet g; g.A1h = a1h; g.A1l = a1l; g.A2h = a2h; g.A2l = a2l; g.K1 = K1;
        g.B = b; g.Cf = cf; g.Chi = ch; g.Clo = cl; g.Lhi = lh; g.Llo = ll;
        g.bias = bias; g.gate = gate; g.act = act; return g;
    };
    auto VS = [](const bf16* ah, const bf16* al, const bf16* b,
                 const bf16* uh, const bf16* ul, bf16* ch, bf16* cl, bf16* nh, bf16* nl) {
        VSet v; v.Ahi = ah; v.Alo = al; v.B = b; v.Uhi = uh; v.Ulo = ul;
        v.Chi = ch; v.Clo = cl; v.Nhi = nh; v.Nlo = nl; return v;
    };

    k_prepack<<<dim3(64, 15), 256>>>(pa);
    k_prep<<<(n * 128 + 255) / 256, 256>>>(h_vec, h_sca, te, tptr, vecS, scaX, n);

    // vi pair: planes + norms
    gemm_vn3<<<dim3(gv, 2), 256>>>(
        VS(vecS, vecS + PV, B_a1Wv1, nullptr, nullptr, viAs, viAs + PV, nA1, nA1 + H64),
        VS(vecS, vecS + PV, B_n1Wv1, nullptr, nullptr, viNs, viNs + PV, nN1, nN1 + H64), n);
    // S pair: A = (norms | sca shared);  net side also emits lrelu(Sn)
    gemm_bf16<256><<<dim3(gv, 2), 512, SM256>>>(
        GS(nA1, nA1 + H64, scaX, scaX + H256, 64, B_a1Ws,
           nullptr, Sas, Sas + H256, nullptr, nullptr, nullptr, nullptr, 0),
        GS(nN1, nN1 + H64, scaX, scaX + H256, 64, B_n1Ws,
           nullptr, Sns, Sns + H256, lrS, lrS + H256, nullptr, nullptr, 0),
        n, 320, n);
    // gates pair
    gemm_bf16<64><<<dim3(gv, 2), 256, SM64>>>(
        GS(Sas, Sas + H256, nullptr, nullptr, 256, B_a1Wg,
           Ga, nullptr, nullptr, nullptr, nullptr, W[8], nullptr, 1),
        GS(Sns, Sns + H256, nullptr, nullptr, 256, B_n1Wg,
           Gn, nullptr, nullptr, nullptr, nullptr, W[19], nullptr, 1),
        n, 256, n);
    // u pair (per-plane rows M3, gated)
    gemm_bf16<64><<<dim3(g3, 2), 256, SM64>>>(
        GS(viAs, viAs + PV, nullptr, nullptr, 64, B_a1Wv2,
           nullptr, uas, uas + PV, nullptr, nullptr, nullptr, Ga, 0),
        GS(viNs, viNs + PV, nullptr, nullptr, 64, B_n1Wv2,
           nullptr, uns, uns + PV, nullptr, nullptr, nullptr, Gn, 0),
        M3, 64, n);
    // d pair with fused vn_lrelu -> v
    gemm_vn3<<<dim3(gv, 2), 256>>>(
        VS(uas, uas + PV, B_a1Wd, uas, uas + PV, vas, vas + PV, nullptr, nullptr),
        VS(uns, uns + PV, B_n1Wd, uns, uns + PV, vns, vns + PV, nullptr, nullptr), n);
    // vi2 pair: att -> norms only; net -> vi2n planes + norms
    gemm_vn3<<<dim3(gv, 2), 256>>>(
        VS(vas, vas + PV, B_a2Wv1, nullptr, nullptr, nullptr, nullptr, nA2, nA2 + H64),
        VS(vns, vns + PV, B_n2Wv1, nullptr, nullptr, viAs, viAs + PV, nN2, nN2 + H64), n);
    k_att<<<(n + 7) / 8, 256>>>(nA2, Sas, W[12], att, n);

    // fs = (norms2 | lrelu(Sn)) @ n2Ws  -> Sas reuse
    {
        GSet g = GS(nN2, nN2 + H64, lrS, lrS + H256, 64, B_n2Ws,
                    nullptr, Sas, Sas + H256, nullptr, nullptr, nullptr, nullptr, 0);
        gemm_bf16<256><<<dim3(gv, 1), 512, SM256>>>(g, g, n, 320, n);
    }
    // gate2 -> Ga reuse
    {
        GSet g = GS(Sas, Sas + H256, nullptr, nullptr, 256, B_n2Wg,
                    Ga, nullptr, nullptr, nullptr, nullptr, W[25], nullptr, 1);
        gemm_bf16<64><<<dim3(gv, 1), 256, SM64>>>(g, g, n, 256, n);
    }
    // fv = gate2 * (n2Wv2 @ vi2n) -> vas reuse
    {
        GSet g = GS(viAs, viAs + PV, nullptr, nullptr, 64, B_n2Wv2,
                    nullptr, vas, vas + PV, nullptr, nullptr, nullptr, Ga, 0);
        gemm_bf16<64><<<dim3(g3, 1), 256, SM64>>>(g, g, M3, 64, n);
    }

    k_segstart<<<(B + 1 + 255) / 256, 256>>>(bid, n, B, segs);
    k_softmax<<<B, 256>>>(att, segs, wgt);
    k_reduce<<<B, 256>>>(wgt, Sas, vas, pos, segs, B, n, (float*)d_out);
}